// round 1
// baseline (speedup 1.0000x reference)
#include <cuda_runtime.h>
#include <cstddef>

#define NN 50000
#define NE 800000
#define HID 256

// ---------------- scratch (device globals: no allocation allowed) ----------------
__device__ float g_a[(size_t)NN * HID];    // relu(x@pre_w1+b1)
__device__ float g_h[(size_t)NN * HID];    // h
__device__ float g_t[(size_t)NN * HID];    // relu(h@conv_w+b)  (per-node edge transform)
__device__ float g_agg[(size_t)NN * HID];  // segment sum
__device__ float g_u[(size_t)NN * HID];    // relu([h,agg]@post_w1+b)
__device__ int   g_cnt[NN];
__device__ int   g_rowptr[NN + 1];
__device__ int   g_fill[NN];
__device__ int   g_col[NE];

// ---------------- generic fp32 GEMM: C = act(concat(A1,A2) @ B + bias) ----------------
// A1: M x K1 row-major, A2: M x (K-K1) row-major (nullptr if K1==K)
// B: K x N row-major. BM=BN=128, BK=16, TM=TN=8, 256 threads.
template <int ACT>
__global__ __launch_bounds__(256) void sgemm_kernel(
    const float* __restrict__ A1, const float* __restrict__ A2,
    const float* __restrict__ B, const float* __restrict__ bias,
    float* __restrict__ C, int M, int N, int K, int K1)
{
    __shared__ float As[16][128];
    __shared__ float Bs[16][128];
    const int tid = threadIdx.x;
    const int m0 = blockIdx.y * 128;
    const int n0 = blockIdx.x * 128;
    const int ty = tid >> 4;        // 0..15 (row group)
    const int tx = tid & 15;        // 0..15 (col group)

    float acc[8][8];
#pragma unroll
    for (int i = 0; i < 8; i++)
#pragma unroll
        for (int j = 0; j < 8; j++) acc[i][j] = 0.f;

    const int arow0 = tid >> 2;         // 0..63
    const int akk   = (tid & 3) * 4;    // 0,4,8,12
    const int brow  = tid >> 4;         // 0..15
    const int bcol  = (tid & 15) * 4;   // 0..60

    for (int k0 = 0; k0 < K; k0 += 16) {
        // choose A source (whole 16-wide k-tile lies entirely in A1 or A2; K1 % 16 == 0)
        const float* Ab; int lda, kof;
        if (k0 < K1) { Ab = A1; lda = K1;     kof = k0; }
        else         { Ab = A2; lda = K - K1; kof = k0 - K1; }

#pragma unroll
        for (int p = 0; p < 2; p++) {
            int row = arow0 + p * 64;
            int gm = m0 + row;
            float4 v = make_float4(0.f, 0.f, 0.f, 0.f);
            if (gm < M) v = *(const float4*)(Ab + (size_t)gm * lda + kof + akk);
            As[akk + 0][row] = v.x;
            As[akk + 1][row] = v.y;
            As[akk + 2][row] = v.z;
            As[akk + 3][row] = v.w;
        }
        {
            const float* bp = B + (size_t)(k0 + brow) * N + n0 + bcol;
            float4 v0 = *(const float4*)(bp);
            float4 v1 = *(const float4*)(bp + 64);
            *(float4*)&Bs[brow][bcol]      = v0;
            *(float4*)&Bs[brow][bcol + 64] = v1;
        }
        __syncthreads();

#pragma unroll
        for (int k = 0; k < 16; k++) {
            float ra[8], rb[8];
            *(float4*)&ra[0] = *(const float4*)&As[k][ty * 8];
            *(float4*)&ra[4] = *(const float4*)&As[k][ty * 8 + 4];
            *(float4*)&rb[0] = *(const float4*)&Bs[k][tx * 8];
            *(float4*)&rb[4] = *(const float4*)&Bs[k][tx * 8 + 4];
#pragma unroll
            for (int i = 0; i < 8; i++)
#pragma unroll
                for (int j = 0; j < 8; j++) acc[i][j] += ra[i] * rb[j];
        }
        __syncthreads();
    }

    float bb[8];
    *(float4*)&bb[0] = *(const float4*)(bias + n0 + tx * 8);
    *(float4*)&bb[4] = *(const float4*)(bias + n0 + tx * 8 + 4);

#pragma unroll
    for (int i = 0; i < 8; i++) {
        int gm = m0 + ty * 8 + i;
        if (gm >= M) break;
        float o[8];
#pragma unroll
        for (int j = 0; j < 8; j++) {
            float v = acc[i][j] + bb[j];
            if (ACT == 1) v = fmaxf(v, 0.f);
            o[j] = v;
        }
        float* cp = C + (size_t)gm * N + n0 + tx * 8;
        *(float4*)(cp)     = *(float4*)&o[0];
        *(float4*)(cp + 4) = *(float4*)&o[4];
    }
}

// ---------------- CSR build ----------------
__global__ void count_kernel(const int* __restrict__ dst, int* __restrict__ cnt) {
    int e = blockIdx.x * blockDim.x + threadIdx.x;
    if (e < NE) atomicAdd(&cnt[dst[e]], 1);
}

__global__ __launch_bounds__(1024) void scan_kernel(const int* __restrict__ cnt,
                                                    int* __restrict__ rowptr,
                                                    int* __restrict__ fill) {
    __shared__ int sdata[1024];
    __shared__ int s_carry;
    const int tid = threadIdx.x;
    if (tid == 0) { s_carry = 0; rowptr[0] = 0; }
    __syncthreads();
    for (int base = 0; base < NN; base += 1024) {
        int i = base + tid;
        int v = (i < NN) ? cnt[i] : 0;
        sdata[tid] = v;
        __syncthreads();
        // Hillis-Steele inclusive scan
#pragma unroll
        for (int off = 1; off < 1024; off <<= 1) {
            int y = (tid >= off) ? sdata[tid - off] : 0;
            __syncthreads();
            sdata[tid] += y;
            __syncthreads();
        }
        int inc = sdata[tid] + s_carry;
        if (i < NN) {
            rowptr[i + 1] = inc;
            fill[i] = inc - v;   // exclusive prefix = CSR row start
        }
        __syncthreads();
        if (tid == 1023) s_carry = inc;
        __syncthreads();
    }
}

__global__ void scatter_kernel(const int* __restrict__ src, const int* __restrict__ dst,
                               int* __restrict__ fill, int* __restrict__ col) {
    int e = blockIdx.x * blockDim.x + threadIdx.x;
    if (e < NE) {
        int slot = atomicAdd(&fill[dst[e]], 1);
        col[slot] = src[e];
    }
}

// ---------------- atomic-free aggregation: one block per node ----------------
__global__ __launch_bounds__(64) void agg_kernel(const float* __restrict__ t,
                                                 const int* __restrict__ rowptr,
                                                 const int* __restrict__ col,
                                                 float* __restrict__ agg) {
    const int node = blockIdx.x;
    const int tid = threadIdx.x;          // 64 threads, float4 each = 256 feats
    const int s = rowptr[node];
    const int e = rowptr[node + 1];
    float4 acc = make_float4(0.f, 0.f, 0.f, 0.f);
    for (int i = s; i < e; i++) {
        int sn = __ldg(&col[i]);
        float4 v = *(const float4*)(t + (size_t)sn * HID + tid * 4);
        acc.x += v.x; acc.y += v.y; acc.z += v.z; acc.w += v.w;
    }
    *(float4*)(agg + (size_t)node * HID + tid * 4) = acc;
}

// ---------------- output projection: out = tanh(u @ W2 + b2), W2: 256x16 ----------------
__global__ __launch_bounds__(256) void out_kernel(const float* __restrict__ u,
                                                  const float* __restrict__ w,
                                                  const float* __restrict__ b,
                                                  float* __restrict__ out, int M) {
    __shared__ float ws[256 * 16];
    __shared__ float bs[16];
    const int tid = threadIdx.x;
    for (int i = tid; i < 256 * 16 / 4; i += 256)
        ((float4*)ws)[i] = ((const float4*)w)[i];
    if (tid < 16) bs[tid] = b[tid];
    __syncthreads();

    const int mloc = tid >> 1;            // 0..127
    const int off  = (tid & 1) * 8;       // half of the 16 outputs
    const int m = blockIdx.x * 128 + mloc;
    if (m >= M) return;

    float acc[8];
#pragma unroll
    for (int j = 0; j < 8; j++) acc[j] = bs[off + j];

    const float4* up = (const float4*)(u + (size_t)m * HID);
#pragma unroll 4
    for (int k4 = 0; k4 < 64; k4++) {
        float4 a = up[k4];
        float av[4] = {a.x, a.y, a.z, a.w};
#pragma unroll
        for (int q = 0; q < 4; q++) {
            const float* wr = &ws[(k4 * 4 + q) * 16 + off];
#pragma unroll
            for (int j = 0; j < 8; j++) acc[j] += av[q] * wr[j];
        }
    }
    float o[8];
#pragma unroll
    for (int j = 0; j < 8; j++) o[j] = tanhf(acc[j]);
    float* op = out + (size_t)m * 16 + off;
    *(float4*)(op)     = *(float4*)&o[0];
    *(float4*)(op + 4) = *(float4*)&o[4];
}

// ---------------- launcher ----------------
extern "C" void kernel_launch(void* const* d_in, const int* in_sizes, int n_in,
                              void* d_out, int out_size) {
    const float* x       = (const float*)d_in[0];
    const int*   ei      = (const int*)d_in[1];   // (2, E) row-major int32
    const float* pre_w1  = (const float*)d_in[2];
    const float* pre_b1  = (const float*)d_in[3];
    const float* pre_w2  = (const float*)d_in[4];
    const float* pre_b2  = (const float*)d_in[5];
    const float* conv_w  = (const float*)d_in[6];
    const float* conv_b  = (const float*)d_in[7];
    const float* post_w1 = (const float*)d_in[8];
    const float* post_b1 = (const float*)d_in[9];
    const float* post_w2 = (const float*)d_in[10];
    const float* post_b2 = (const float*)d_in[11];
    float* out = (float*)d_out;

    const int* src = ei;
    const int* dst = ei + NE;

    float *a, *h, *t, *agg, *u;
    int *cnt, *rowptr, *fill, *col;
    cudaGetSymbolAddress((void**)&a,      g_a);
    cudaGetSymbolAddress((void**)&h,      g_h);
    cudaGetSymbolAddress((void**)&t,      g_t);
    cudaGetSymbolAddress((void**)&agg,    g_agg);
    cudaGetSymbolAddress((void**)&u,      g_u);
    cudaGetSymbolAddress((void**)&cnt,    g_cnt);
    cudaGetSymbolAddress((void**)&rowptr, g_rowptr);
    cudaGetSymbolAddress((void**)&fill,   g_fill);
    cudaGetSymbolAddress((void**)&col,    g_col);

    cudaMemsetAsync(cnt, 0, NN * sizeof(int), 0);

    dim3 ggemm(HID / 128, (NN + 127) / 128);  // (2, 391)

    // pre-MLP
    sgemm_kernel<1><<<ggemm, 256>>>(x, nullptr, pre_w1, pre_b1, a, NN, HID, 16, 16);
    sgemm_kernel<0><<<ggemm, 256>>>(a, nullptr, pre_w2, pre_b2, h, NN, HID, HID, HID);

    // per-NODE edge transform (hoisted out of the per-edge loop):
    // msg_e = relu(W h_src + b) = t[src],  t = relu(h @ conv_w + conv_b)
    sgemm_kernel<1><<<ggemm, 256>>>(h, nullptr, conv_w, conv_b, t, NN, HID, HID, HID);

    // CSR build + atomic-free segment sum
    count_kernel<<<(NE + 255) / 256, 256>>>(dst, cnt);
    scan_kernel<<<1, 1024>>>(cnt, rowptr, fill);
    scatter_kernel<<<(NE + 255) / 256, 256>>>(src, dst, fill, col);
    agg_kernel<<<NN, 64>>>(t, rowptr, col, agg);

    // post-MLP: concat handled inside the GEMM (A1=h, A2=agg, K=512)
    sgemm_kernel<1><<<ggemm, 256>>>(h, agg, post_w1, post_b1, u, NN, HID, 2 * HID, HID);
    out_kernel<<<(NN + 127) / 128, 256>>>(u, post_w2, post_b2, out, NN);
}

// round 3
// speedup vs baseline: 1.5010x; 1.5010x over previous
#include <cuda_runtime.h>
#include <cuda_bf16.h>
#include <cstdint>
#include <cstddef>

#define NN 50000
#define NE 800000
#define HID 256

// smem stage layout (bytes): Ah[128x40 bf16]=10240 | Al=10240 | Bh[128x40]=10240 | Bl=10240
#define STAGE_B 40960

// ---------------- scratch (device globals: no allocation allowed) ----------------
__device__ float g_a[(size_t)NN * HID];    // relu(x@pre_w1+b1)
__device__ float g_h[(size_t)NN * HID];    // h
__device__ float g_t[(size_t)NN * HID];    // relu(h@conv_w+b)
__device__ float g_agg[(size_t)NN * HID];  // segment sum
__device__ float g_u[(size_t)NN * HID];    // relu([h,agg]@post_w1+b)
__device__ int   g_cnt[NN];
__device__ int   g_rowptr[NN + 1];
__device__ int   g_fill[NN];
__device__ int   g_col[NE];
// split/transposed weights: [N=256][K] bf16, hi+lo
__device__ __nv_bfloat16 g_w2h[256 * 256], g_w2l[256 * 256];
__device__ __nv_bfloat16 g_wch[256 * 256], g_wcl[256 * 256];
__device__ __nv_bfloat16 g_wph[256 * 512], g_wpl[256 * 512];

// ---------------- weight prep: W[K][N] fp32 -> Wt_hi/Wt_lo [N][K] bf16 ----------------
__global__ void prep_kernel(const float* __restrict__ W, __nv_bfloat16* __restrict__ hi,
                            __nv_bfloat16* __restrict__ lo, int K, int N) {
    __shared__ float tile[32][33];
    int k0 = blockIdx.y * 32, n0 = blockIdx.x * 32;
    int tx = threadIdx.x, ty = threadIdx.y;  // 32 x 8
    for (int i = ty; i < 32; i += 8) tile[i][tx] = W[(size_t)(k0 + i) * N + n0 + tx];
    __syncthreads();
    for (int i = ty; i < 32; i += 8) {
        float v = tile[tx][i];  // = W[k0+tx][n0+i]
        __nv_bfloat16 h = __float2bfloat16_rn(v);
        float res = v - __bfloat162float(h);
        hi[(size_t)(n0 + i) * K + k0 + tx] = h;
        lo[(size_t)(n0 + i) * K + k0 + tx] = __float2bfloat16_rn(res);
    }
}

// ---------------- mma.sync m16n8k16 bf16 macro ----------------
#define MMA_BF16(cc, aa, b0v, b1v)                                              \
    asm volatile(                                                               \
        "mma.sync.aligned.m16n8k16.row.col.f32.bf16.bf16.f32 "                  \
        "{%0,%1,%2,%3}, {%4,%5,%6,%7}, {%8,%9}, {%0,%1,%2,%3};"                 \
        : "+f"(cc[0]), "+f"(cc[1]), "+f"(cc[2]), "+f"(cc[3])                    \
        : "r"(aa[0]), "r"(aa[1]), "r"(aa[2]), "r"(aa[3]), "r"(b0v), "r"(b1v))

__device__ __forceinline__ uint32_t pack_bf16x2(float a, float b) {
    __nv_bfloat162 p = __float22bfloat162_rn(make_float2(a, b));
    return *reinterpret_cast<uint32_t*>(&p);
}

// ---------------- tensor-core GEMM: C = act(concat(A1,A2) @ W + bias) ----------------
// Wh/Wl: [N][K] bf16 (hi + residual-lo).  N = 256 (grid.x = 2, BN=128).
// 3-pass bf16 split: hi*hi + lo*hi + hi*lo, fp32 accumulate.
template <int ACT>
__global__ __launch_bounds__(256) void mma_gemm(
    const float* __restrict__ A1, const float* __restrict__ A2,
    const __nv_bfloat16* __restrict__ Wh, const __nv_bfloat16* __restrict__ Wl,
    const float* __restrict__ bias, float* __restrict__ C, int M, int K, int K1)
{
    extern __shared__ char smc[];
    __shared__ float sbias[128];

    const int tid = threadIdx.x;
    const int wid = tid >> 5, lane = tid & 31;
    const int g = lane >> 2, tg = lane & 3;
    const int wm = wid >> 1, wn = wid & 1;
    const int m0 = blockIdx.y * 128, n0 = blockIdx.x * 128;

    if (tid < 128) sbias[tid] = bias[n0 + tid];

    const int arow = tid >> 1;           // 0..127
    const int aks  = (tid & 1) * 16;     // k sub-offset {0,16}
    const int gm   = m0 + arow;

    float acc[2][8][4];
#pragma unroll
    for (int i = 0; i < 2; i++)
#pragma unroll
        for (int j = 0; j < 8; j++)
#pragma unroll
            for (int q = 0; q < 4; q++) acc[i][j][q] = 0.f;

    const int NC = K >> 5;   // chunks of BK=32
    float va[16];
    uint4 vbh[2], vbl[2];

    auto GLOAD = [&](int c) {
        int ck = c * 32;
        const float* Ap; int lda, kof;
        if (ck < K1) { Ap = A1; lda = K1;     kof = ck; }
        else         { Ap = A2; lda = K - K1; kof = ck - K1; }
        if (gm < M) {
            const float4* p = (const float4*)(Ap + (size_t)gm * lda + kof + aks);
#pragma unroll
            for (int u = 0; u < 4; u++) *(float4*)&va[u * 4] = p[u];
        } else {
#pragma unroll
            for (int u = 0; u < 16; u++) va[u] = 0.f;
        }
        const uint4* ph = (const uint4*)(Wh + (size_t)(n0 + arow) * K + ck + aks);
        const uint4* pl = (const uint4*)(Wl + (size_t)(n0 + arow) * K + ck + aks);
        vbh[0] = ph[0]; vbh[1] = ph[1];
        vbl[0] = pl[0]; vbl[1] = pl[1];
    };

    auto SSTORE = [&](int s) {
        char* base = smc + s * STAGE_B;
        uint32_t hw[8], lw[8];
#pragma unroll
        for (int i = 0; i < 8; i++) {
            float f0 = va[2 * i], f1 = va[2 * i + 1];
            float h0 = __bfloat162float(__float2bfloat16_rn(f0));
            float h1 = __bfloat162float(__float2bfloat16_rn(f1));
            hw[i] = pack_bf16x2(h0, h1);
            lw[i] = pack_bf16x2(f0 - h0, f1 - h1);
        }
        char* pa = base + arow * 80 + aks * 2;
#pragma unroll
        for (int i = 0; i < 4; i++) {
            *(uint2*)(pa + 8 * i)         = make_uint2(hw[2 * i], hw[2 * i + 1]);
            *(uint2*)(pa + 10240 + 8 * i) = make_uint2(lw[2 * i], lw[2 * i + 1]);
        }
        char* pb = base + 20480 + arow * 80 + aks * 2;
        *(uint4*)(pb)          = vbh[0];
        *(uint4*)(pb + 16)     = vbh[1];
        *(uint4*)(pb + 10240)      = vbl[0];
        *(uint4*)(pb + 10240 + 16) = vbl[1];
    };

    GLOAD(0);
    SSTORE(0);
    __syncthreads();

    for (int c = 0; c < NC; c++) {
        if (c + 1 < NC) GLOAD(c + 1);

        const char* so = smc + (c & 1) * STAGE_B;
#pragma unroll
        for (int ks = 0; ks < 2; ks++) {
            const int kb2 = (ks * 16 + tg * 2) * 2;   // byte offset of k in row
            uint32_t ah[2][4];
#pragma unroll
            for (int i = 0; i < 2; i++) {
                const char* p = so + (wm * 32 + i * 16 + g) * 80 + kb2;
                ah[i][0] = *(const uint32_t*)(p);
                ah[i][1] = *(const uint32_t*)(p + 640);
                ah[i][2] = *(const uint32_t*)(p + 16);
                ah[i][3] = *(const uint32_t*)(p + 656);
            }
            uint32_t bb[8][2];
#pragma unroll
            for (int j = 0; j < 8; j++) {
                const char* p = so + 20480 + (wn * 64 + j * 8 + g) * 80 + kb2;
                bb[j][0] = *(const uint32_t*)(p);
                bb[j][1] = *(const uint32_t*)(p + 16);
            }
#pragma unroll
            for (int i = 0; i < 2; i++)
#pragma unroll
                for (int j = 0; j < 8; j++) MMA_BF16(acc[i][j], ah[i], bb[j][0], bb[j][1]);

            uint32_t al[2][4];
#pragma unroll
            for (int i = 0; i < 2; i++) {
                const char* p = so + 10240 + (wm * 32 + i * 16 + g) * 80 + kb2;
                al[i][0] = *(const uint32_t*)(p);
                al[i][1] = *(const uint32_t*)(p + 640);
                al[i][2] = *(const uint32_t*)(p + 16);
                al[i][3] = *(const uint32_t*)(p + 656);
            }
#pragma unroll
            for (int i = 0; i < 2; i++)
#pragma unroll
                for (int j = 0; j < 8; j++) MMA_BF16(acc[i][j], al[i], bb[j][0], bb[j][1]);

#pragma unroll
            for (int j = 0; j < 8; j++) {
                const char* p = so + 30720 + (wn * 64 + j * 8 + g) * 80 + kb2;
                bb[j][0] = *(const uint32_t*)(p);
                bb[j][1] = *(const uint32_t*)(p + 16);
            }
#pragma unroll
            for (int i = 0; i < 2; i++)
#pragma unroll
                for (int j = 0; j < 8; j++) MMA_BF16(acc[i][j], ah[i], bb[j][0], bb[j][1]);
        }

        if (c + 1 < NC) SSTORE((c + 1) & 1);
        __syncthreads();
    }

    // epilogue: bias + activation + store
#pragma unroll
    for (int i = 0; i < 2; i++) {
        int r0 = m0 + wm * 32 + i * 16 + g;
#pragma unroll
        for (int j = 0; j < 8; j++) {
            int cl = wn * 64 + j * 8 + tg * 2;
            float b0 = sbias[cl], b1 = sbias[cl + 1];
            float v0 = acc[i][j][0] + b0, v1 = acc[i][j][1] + b1;
            float v2 = acc[i][j][2] + b0, v3 = acc[i][j][3] + b1;
            if (ACT == 1) {
                v0 = fmaxf(v0, 0.f); v1 = fmaxf(v1, 0.f);
                v2 = fmaxf(v2, 0.f); v3 = fmaxf(v3, 0.f);
            }
            if (r0 < M)     *(float2*)(C + (size_t)r0 * 256 + n0 + cl)       = make_float2(v0, v1);
            if (r0 + 8 < M) *(float2*)(C + (size_t)(r0 + 8) * 256 + n0 + cl) = make_float2(v2, v3);
        }
    }
}

// ---------------- fp32 GEMM (used only for pre1, K=16) ----------------
template <int ACT>
__global__ __launch_bounds__(256) void sgemm_kernel(
    const float* __restrict__ A1, const float* __restrict__ B, const float* __restrict__ bias,
    float* __restrict__ C, int M, int N, int K)
{
    __shared__ float As[16][128];
    __shared__ float Bs[16][128];
    const int tid = threadIdx.x;
    const int m0 = blockIdx.y * 128;
    const int n0 = blockIdx.x * 128;
    const int ty = tid >> 4;
    const int tx = tid & 15;

    float acc[8][8];
#pragma unroll
    for (int i = 0; i < 8; i++)
#pragma unroll
        for (int j = 0; j < 8; j++) acc[i][j] = 0.f;

    const int arow0 = tid >> 2;
    const int akk   = (tid & 3) * 4;
    const int brow  = tid >> 4;
    const int bcol  = (tid & 15) * 4;

    for (int k0 = 0; k0 < K; k0 += 16) {
#pragma unroll
        for (int p = 0; p < 2; p++) {
            int row = arow0 + p * 64;
            int gmm = m0 + row;
            float4 v = make_float4(0.f, 0.f, 0.f, 0.f);
            if (gmm < M) v = *(const float4*)(A1 + (size_t)gmm * K + k0 + akk);
            As[akk + 0][row] = v.x;
            As[akk + 1][row] = v.y;
            As[akk + 2][row] = v.z;
            As[akk + 3][row] = v.w;
        }
        {
            const float* bp = B + (size_t)(k0 + brow) * N + n0 + bcol;
            float4 v0 = *(const float4*)(bp);
            float4 v1 = *(const float4*)(bp + 64);
            *(float4*)&Bs[brow][bcol]      = v0;
            *(float4*)&Bs[brow][bcol + 64] = v1;
        }
        __syncthreads();
#pragma unroll
        for (int k = 0; k < 16; k++) {
            float ra[8], rb[8];
            *(float4*)&ra[0] = *(const float4*)&As[k][ty * 8];
            *(float4*)&ra[4] = *(const float4*)&As[k][ty * 8 + 4];
            *(float4*)&rb[0] = *(const float4*)&Bs[k][tx * 8];
            *(float4*)&rb[4] = *(const float4*)&Bs[k][tx * 8 + 4];
#pragma unroll
            for (int i = 0; i < 8; i++)
#pragma unroll
                for (int j = 0; j < 8; j++) acc[i][j] += ra[i] * rb[j];
        }
        __syncthreads();
    }

    float bb[8];
    *(float4*)&bb[0] = *(const float4*)(bias + n0 + tx * 8);
    *(float4*)&bb[4] = *(const float4*)(bias + n0 + tx * 8 + 4);
#pragma unroll
    for (int i = 0; i < 8; i++) {
        int gmm = m0 + ty * 8 + i;
        if (gmm >= M) break;
        float o[8];
#pragma unroll
        for (int j = 0; j < 8; j++) {
            float v = acc[i][j] + bb[j];
            if (ACT == 1) v = fmaxf(v, 0.f);
            o[j] = v;
        }
        float* cp = C + (size_t)gmm * N + n0 + tx * 8;
        *(float4*)(cp)     = *(float4*)&o[0];
        *(float4*)(cp + 4) = *(float4*)&o[4];
    }
}

// ---------------- CSR build ----------------
__global__ void count_kernel(const int* __restrict__ dst, int* __restrict__ cnt) {
    int e = blockIdx.x * blockDim.x + threadIdx.x;
    if (e < NE) atomicAdd(&cnt[dst[e]], 1);
}

__global__ __launch_bounds__(1024) void scan_kernel(const int* __restrict__ cnt,
                                                    int* __restrict__ rowptr,
                                                    int* __restrict__ fill) {
    __shared__ int sdata[1024];
    __shared__ int s_carry;
    const int tid = threadIdx.x;
    if (tid == 0) { s_carry = 0; rowptr[0] = 0; }
    __syncthreads();
    for (int base = 0; base < NN; base += 1024) {
        int i = base + tid;
        int v = (i < NN) ? cnt[i] : 0;
        sdata[tid] = v;
        __syncthreads();
#pragma unroll
        for (int off = 1; off < 1024; off <<= 1) {
            int y = (tid >= off) ? sdata[tid - off] : 0;
            __syncthreads();
            sdata[tid] += y;
            __syncthreads();
        }
        int inc = sdata[tid] + s_carry;
        if (i < NN) {
            rowptr[i + 1] = inc;
            fill[i] = inc - v;
        }
        __syncthreads();
        if (tid == 1023) s_carry = inc;
        __syncthreads();
    }
}

__global__ void scatter_kernel(const int* __restrict__ src, const int* __restrict__ dst,
                               int* __restrict__ fill, int* __restrict__ col) {
    int e = blockIdx.x * blockDim.x + threadIdx.x;
    if (e < NE) {
        int slot = atomicAdd(&fill[dst[e]], 1);
        col[slot] = src[e];
    }
}

// ---------------- atomic-free aggregation ----------------
__global__ __launch_bounds__(64) void agg_kernel(const float* __restrict__ t,
                                                 const int* __restrict__ rowptr,
                                                 const int* __restrict__ col,
                                                 float* __restrict__ agg) {
    const int node = blockIdx.x;
    const int tid = threadIdx.x;
    const int s = rowptr[node];
    const int e = rowptr[node + 1];
    float4 acc = make_float4(0.f, 0.f, 0.f, 0.f);
    for (int i = s; i < e; i++) {
        int sn = __ldg(&col[i]);
        float4 v = *(const float4*)(t + (size_t)sn * HID + tid * 4);
        acc.x += v.x; acc.y += v.y; acc.z += v.z; acc.w += v.w;
    }
    *(float4*)(agg + (size_t)node * HID + tid * 4) = acc;
}

// ---------------- output projection ----------------
__global__ __launch_bounds__(256) void out_kernel(const float* __restrict__ u,
                                                  const float* __restrict__ w,
                                                  const float* __restrict__ b,
                                                  float* __restrict__ out, int M) {
    __shared__ float ws[256 * 16];
    __shared__ float bs[16];
    const int tid = threadIdx.x;
    for (int i = tid; i < 256 * 16 / 4; i += 256)
        ((float4*)ws)[i] = ((const float4*)w)[i];
    if (tid < 16) bs[tid] = b[tid];
    __syncthreads();

    const int mloc = tid >> 1;
    const int off  = (tid & 1) * 8;
    const int m = blockIdx.x * 128 + mloc;
    if (m >= M) return;

    float acc[8];
#pragma unroll
    for (int j = 0; j < 8; j++) acc[j] = bs[off + j];

    const float4* up = (const float4*)(u + (size_t)m * HID);
#pragma unroll 4
    for (int k4 = 0; k4 < 64; k4++) {
        float4 a = up[k4];
        float av[4] = {a.x, a.y, a.z, a.w};
#pragma unroll
        for (int q = 0; q < 4; q++) {
            const float* wr = &ws[(k4 * 4 + q) * 16 + off];
#pragma unroll
            for (int j = 0; j < 8; j++) acc[j] += av[q] * wr[j];
        }
    }
    float o[8];
#pragma unroll
    for (int j = 0; j < 8; j++) o[j] = tanhf(acc[j]);
    float* op = out + (size_t)m * 16 + off;
    *(float4*)(op)     = *(float4*)&o[0];
    *(float4*)(op + 4) = *(float4*)&o[4];
}

// ---------------- launcher ----------------
extern "C" void kernel_launch(void* const* d_in, const int* in_sizes, int n_in,
                              void* d_out, int out_size) {
    const float* x       = (const float*)d_in[0];
    const int*   ei      = (const int*)d_in[1];
    const float* pre_w1  = (const float*)d_in[2];
    const float* pre_b1  = (const float*)d_in[3];
    const float* pre_w2  = (const float*)d_in[4];
    const float* pre_b2  = (const float*)d_in[5];
    const float* conv_w  = (const float*)d_in[6];
    const float* conv_b  = (const float*)d_in[7];
    const float* post_w1 = (const float*)d_in[8];
    const float* post_b1 = (const float*)d_in[9];
    const float* post_w2 = (const float*)d_in[10];
    const float* post_b2 = (const float*)d_in[11];
    float* out = (float*)d_out;

    const int* src = ei;
    const int* dst = ei + NE;

    float *a, *h, *t, *agg, *u;
    int *cnt, *rowptr, *fill, *col;
    __nv_bfloat16 *w2h, *w2l, *wch, *wcl, *wph, *wpl;
    cudaGetSymbolAddress((void**)&a,      g_a);
    cudaGetSymbolAddress((void**)&h,      g_h);
    cudaGetSymbolAddress((void**)&t,      g_t);
    cudaGetSymbolAddress((void**)&agg,    g_agg);
    cudaGetSymbolAddress((void**)&u,      g_u);
    cudaGetSymbolAddress((void**)&cnt,    g_cnt);
    cudaGetSymbolAddress((void**)&rowptr, g_rowptr);
    cudaGetSymbolAddress((void**)&fill,   g_fill);
    cudaGetSymbolAddress((void**)&col,    g_col);
    cudaGetSymbolAddress((void**)&w2h,    g_w2h);
    cudaGetSymbolAddress((void**)&w2l,    g_w2l);
    cudaGetSymbolAddress((void**)&wch,    g_wch);
    cudaGetSymbolAddress((void**)&wcl,    g_wcl);
    cudaGetSymbolAddress((void**)&wph,    g_wph);
    cudaGetSymbolAddress((void**)&wpl,    g_wpl);

    const int DSMEM = 2 * STAGE_B;  // 80 KB
    cudaFuncSetAttribute(mma_gemm<0>, cudaFuncAttributeMaxDynamicSharedMemorySize, DSMEM);
    cudaFuncSetAttribute(mma_gemm<1>, cudaFuncAttributeMaxDynamicSharedMemorySize, DSMEM);

    cudaMemsetAsync(cnt, 0, NN * sizeof(int), 0);

    // weight prep (transpose + bf16 hi/lo split)
    dim3 pb(32, 8);
    prep_kernel<<<dim3(256 / 32, 256 / 32), pb>>>(pre_w2,  w2h, w2l, 256, 256);
    prep_kernel<<<dim3(256 / 32, 256 / 32), pb>>>(conv_w,  wch, wcl, 256, 256);
    prep_kernel<<<dim3(256 / 32, 512 / 32), pb>>>(post_w1, wph, wpl, 512, 256);

    const int MT = (NN + 127) / 128;  // 391
    dim3 gg(2, MT);

    // pre-MLP layer 1 (K=16, fp32 FFMA)
    sgemm_kernel<1><<<dim3(2, MT), 256>>>(x, pre_w1, pre_b1, a, NN, HID, 16);
    // pre-MLP layer 2 (tensor core)
    mma_gemm<0><<<gg, 256, DSMEM>>>(a, nullptr, w2h, w2l, pre_b2, h, NN, 256, 256);
    // per-node edge transform (tensor core)
    mma_gemm<1><<<gg, 256, DSMEM>>>(h, nullptr, wch, wcl, conv_b, t, NN, 256, 256);

    // CSR build + atomic-free segment sum
    count_kernel<<<(NE + 255) / 256, 256>>>(dst, cnt);
    scan_kernel<<<1, 1024>>>(cnt, rowptr, fill);
    scatter_kernel<<<(NE + 255) / 256, 256>>>(src, dst, fill, col);
    agg_kernel<<<NN, 64>>>(t, rowptr, col, agg);

    // post-MLP layer 1 (tensor core, K=512 concat)
    mma_gemm<1><<<gg, 256, DSMEM>>>(h, agg, wph, wpl, post_b1, u, NN, 512, 256);
    // output projection + tanh
    out_kernel<<<(NN + 127) / 128, 256>>>(u, post_w2, post_b2, out, NN);
}

// round 4
// speedup vs baseline: 1.5983x; 1.0648x over previous
#include <cuda_runtime.h>
#include <cuda_bf16.h>
#include <cstdint>
#include <cstddef>

#define NN 50000
#define NE 800000
#define HID 256

// smem stage layout (bytes, pitch 80/row of 32 bf16 + pad):
// Ah[128x80]=10240 | Al=10240 | Bh[128x80]=10240 | Bl=10240
#define STAGE_B 40960

// ---------------- scratch (device globals: no allocation allowed) ----------------
__device__ __nv_bfloat16 g_ah[(size_t)NN * HID], g_al[(size_t)NN * HID];
__device__ __nv_bfloat16 g_hh[(size_t)NN * HID], g_hl[(size_t)NN * HID];
__device__ __nv_bfloat16 g_th[(size_t)NN * HID], g_tl[(size_t)NN * HID];
__device__ __nv_bfloat16 g_gh[(size_t)NN * HID], g_gl[(size_t)NN * HID];
__device__ __nv_bfloat16 g_uh[(size_t)NN * HID], g_ul[(size_t)NN * HID];
__device__ int g_cnt[NN];
__device__ int g_rowptr[NN + 1];
__device__ int g_fill[NN];
__device__ int g_col[NE];
// split/transposed weights: [N=256][K] bf16, hi+lo
__device__ __nv_bfloat16 g_w2h[256 * 256], g_w2l[256 * 256];
__device__ __nv_bfloat16 g_wch[256 * 256], g_wcl[256 * 256];
__device__ __nv_bfloat16 g_wph[256 * 512], g_wpl[256 * 512];

// ---------------- helpers ----------------
__device__ __forceinline__ uint32_t s2u(const void* p) {
    uint32_t a;
    asm("{ .reg .u64 t; cvta.to.shared.u64 t, %1; cvt.u32.u64 %0, t; }" : "=r"(a) : "l"(p));
    return a;
}
__device__ __forceinline__ void cp16(uint32_t dst, const void* src, int srcsz) {
    asm volatile("cp.async.cg.shared.global [%0], [%1], 16, %2;"
                 :: "r"(dst), "l"(src), "r"(srcsz) : "memory");
}
#define CP_COMMIT() asm volatile("cp.async.commit_group;" ::: "memory")

__device__ __forceinline__ void ldsm4(uint32_t& r0, uint32_t& r1, uint32_t& r2, uint32_t& r3,
                                      uint32_t addr) {
    asm volatile("ldmatrix.sync.aligned.m8n8.x4.shared.b16 {%0,%1,%2,%3}, [%4];"
                 : "=r"(r0), "=r"(r1), "=r"(r2), "=r"(r3) : "r"(addr));
}

#define MMA_BF16(cc, aa, b0v, b1v)                                              \
    asm volatile(                                                               \
        "mma.sync.aligned.m16n8k16.row.col.f32.bf16.bf16.f32 "                  \
        "{%0,%1,%2,%3}, {%4,%5,%6,%7}, {%8,%9}, {%0,%1,%2,%3};"                 \
        : "+f"(cc[0]), "+f"(cc[1]), "+f"(cc[2]), "+f"(cc[3])                    \
        : "r"(aa[0]), "r"(aa[1]), "r"(aa[2]), "r"(aa[3]), "r"(b0v), "r"(b1v))

__device__ __forceinline__ uint32_t pack_bf16x2(float a, float b) {
    __nv_bfloat162 p = __float22bfloat162_rn(make_float2(a, b));
    return *reinterpret_cast<uint32_t*>(&p);
}
// split (v0,v1) into hi-pair word + lo-residual-pair word
__device__ __forceinline__ void split_pair(float v0, float v1, uint32_t& hw, uint32_t& lw) {
    float h0 = __bfloat162float(__float2bfloat16_rn(v0));
    float h1 = __bfloat162float(__float2bfloat16_rn(v1));
    hw = pack_bf16x2(h0, h1);
    lw = pack_bf16x2(v0 - h0, v1 - h1);
}

// ---------------- weight prep: W[K][N] fp32 -> Wt_hi/Wt_lo [N][K] bf16 ----------------
__global__ void prep_kernel(const float* __restrict__ W, __nv_bfloat16* __restrict__ hi,
                            __nv_bfloat16* __restrict__ lo, int K, int N) {
    __shared__ float tile[32][33];
    int k0 = blockIdx.y * 32, n0 = blockIdx.x * 32;
    int tx = threadIdx.x, ty = threadIdx.y;  // 32 x 8
    for (int i = ty; i < 32; i += 8) tile[i][tx] = W[(size_t)(k0 + i) * N + n0 + tx];
    __syncthreads();
    for (int i = ty; i < 32; i += 8) {
        float v = tile[tx][i];  // = W[k0+tx][n0+i]
        __nv_bfloat16 h = __float2bfloat16_rn(v);
        hi[(size_t)(n0 + i) * K + k0 + tx] = h;
        lo[(size_t)(n0 + i) * K + k0 + tx] = __float2bfloat16_rn(v - __bfloat162float(h));
    }
}

// ---------------- tensor-core GEMM: C(hi/lo) = act(concat(A1,A2) @ W + bias) ----------
// All operands bf16 hi/lo pairs. BM=128, BN=128 (grid.x=2 for N=256), BK=32.
template <int ACT>
__global__ __launch_bounds__(256) void mma_gemm(
    const __nv_bfloat16* __restrict__ A1h, const __nv_bfloat16* __restrict__ A1l,
    const __nv_bfloat16* __restrict__ A2h, const __nv_bfloat16* __restrict__ A2l,
    const __nv_bfloat16* __restrict__ Wh,  const __nv_bfloat16* __restrict__ Wl,
    const float* __restrict__ bias,
    __nv_bfloat16* __restrict__ Ch, __nv_bfloat16* __restrict__ Cl,
    int M, int K, int K1)
{
    extern __shared__ char smc[];
    __shared__ float sbias[128];

    const int tid = threadIdx.x;
    const int wid = tid >> 5, lane = tid & 31;
    const int g = lane >> 2, tg = lane & 3;
    const int wm = wid >> 1, wn = wid & 1;
    const int m0 = blockIdx.y * 128, n0 = blockIdx.x * 128;
    const uint32_t smc_u = s2u(smc);

    if (tid < 128) sbias[tid] = bias[n0 + tid];

    // staging thread mapping: 2 threads per row, 16 k-elements (32B) each
    const int arow = tid >> 1;
    const int aks  = (tid & 1) * 16;
    const int gm   = m0 + arow;
    const int okA  = (gm < M) ? 16 : 0;

    // ldmatrix per-lane address bases
    const int q = lane >> 3, rr = lane & 7;
    const uint32_t aoff0 = (uint32_t)((wm * 32 + (q & 1) * 8 + rr) * 80 + (q >> 1) * 16);
    const uint32_t boff0 = (uint32_t)(20480 + (wn * 64 + (q >> 1) * 8 + rr) * 80 + (q & 1) * 16);

    float acc[2][8][4];
#pragma unroll
    for (int i = 0; i < 2; i++)
#pragma unroll
        for (int j = 0; j < 8; j++)
#pragma unroll
            for (int p = 0; p < 4; p++) acc[i][j][p] = 0.f;

    const int NC = K >> 5;

    auto STAGE = [&](int c) {
        const int ck = c * 32;
        const __nv_bfloat16 *Ah, *Al; int lda, kof;
        if (ck < K1) { Ah = A1h; Al = A1l; lda = K1;     kof = ck; }
        else         { Ah = A2h; Al = A2l; lda = K - K1; kof = ck - K1; }
        const uint32_t sb = smc_u + (uint32_t)((c & 1) * STAGE_B);
        const uint32_t da = sb + (uint32_t)(arow * 80 + (tid & 1) * 32);
        const __nv_bfloat16* pah = Ah + (size_t)gm * lda + kof + aks;
        const __nv_bfloat16* pal = Al + (size_t)gm * lda + kof + aks;
        cp16(da, pah, okA);               cp16(da + 16, pah + 8, okA);
        cp16(da + 10240, pal, okA);       cp16(da + 10240 + 16, pal + 8, okA);
        const __nv_bfloat16* pbh = Wh + (size_t)(n0 + arow) * K + ck + aks;
        const __nv_bfloat16* pbl = Wl + (size_t)(n0 + arow) * K + ck + aks;
        cp16(da + 20480, pbh, 16);        cp16(da + 20480 + 16, pbh + 8, 16);
        cp16(da + 30720, pbl, 16);        cp16(da + 30720 + 16, pbl + 8, 16);
        CP_COMMIT();
    };

    STAGE(0);

    for (int c = 0; c < NC; c++) {
        if (c + 1 < NC) {
            STAGE(c + 1);
            asm volatile("cp.async.wait_group 1;" ::: "memory");
        } else {
            asm volatile("cp.async.wait_group 0;" ::: "memory");
        }
        __syncthreads();

        const uint32_t sb = smc_u + (uint32_t)((c & 1) * STAGE_B);
#pragma unroll
        for (int ks = 0; ks < 2; ks++) {
            const uint32_t ko = (uint32_t)(ks * 32);
            uint32_t ah[2][4], bb[8][2];
            ldsm4(ah[0][0], ah[0][1], ah[0][2], ah[0][3], sb + aoff0 + ko);
            ldsm4(ah[1][0], ah[1][1], ah[1][2], ah[1][3], sb + aoff0 + 1280 + ko);
#pragma unroll
            for (int jp = 0; jp < 4; jp++)
                ldsm4(bb[2 * jp][0], bb[2 * jp][1], bb[2 * jp + 1][0], bb[2 * jp + 1][1],
                      sb + boff0 + (uint32_t)(jp * 1280) + ko);
#pragma unroll
            for (int i = 0; i < 2; i++)
#pragma unroll
                for (int j = 0; j < 8; j++) MMA_BF16(acc[i][j], ah[i], bb[j][0], bb[j][1]);

            uint32_t al[2][4];
            ldsm4(al[0][0], al[0][1], al[0][2], al[0][3], sb + 10240 + aoff0 + ko);
            ldsm4(al[1][0], al[1][1], al[1][2], al[1][3], sb + 10240 + aoff0 + 1280 + ko);
#pragma unroll
            for (int i = 0; i < 2; i++)
#pragma unroll
                for (int j = 0; j < 8; j++) MMA_BF16(acc[i][j], al[i], bb[j][0], bb[j][1]);

#pragma unroll
            for (int jp = 0; jp < 4; jp++)
                ldsm4(bb[2 * jp][0], bb[2 * jp][1], bb[2 * jp + 1][0], bb[2 * jp + 1][1],
                      sb + 10240 + boff0 + (uint32_t)(jp * 1280) + ko);
#pragma unroll
            for (int i = 0; i < 2; i++)
#pragma unroll
                for (int j = 0; j < 8; j++) MMA_BF16(acc[i][j], ah[i], bb[j][0], bb[j][1]);
        }
        __syncthreads();
    }

    // epilogue: bias + activation + hi/lo split store
#pragma unroll
    for (int i = 0; i < 2; i++) {
        int r0 = m0 + wm * 32 + i * 16 + g;
#pragma unroll
        for (int j = 0; j < 8; j++) {
            int cl = wn * 64 + j * 8 + tg * 2;
            float b0 = sbias[cl], b1 = sbias[cl + 1];
            float v0 = acc[i][j][0] + b0, v1 = acc[i][j][1] + b1;
            float v2 = acc[i][j][2] + b0, v3 = acc[i][j][3] + b1;
            if (ACT == 1) {
                v0 = fmaxf(v0, 0.f); v1 = fmaxf(v1, 0.f);
                v2 = fmaxf(v2, 0.f); v3 = fmaxf(v3, 0.f);
            }
            uint32_t hw, lw;
            if (r0 < M) {
                split_pair(v0, v1, hw, lw);
                *(uint32_t*)(Ch + (size_t)r0 * 256 + n0 + cl) = hw;
                *(uint32_t*)(Cl + (size_t)r0 * 256 + n0 + cl) = lw;
            }
            if (r0 + 8 < M) {
                split_pair(v2, v3, hw, lw);
                *(uint32_t*)(Ch + (size_t)(r0 + 8) * 256 + n0 + cl) = hw;
                *(uint32_t*)(Cl + (size_t)(r0 + 8) * 256 + n0 + cl) = lw;
            }
        }
    }
}

// ---------------- pre-MLP layer 1: fp32 FFMA (K=16), emits hi/lo pair --------------
__global__ __launch_bounds__(256) void sgemm_pre(
    const float* __restrict__ A1, const float* __restrict__ B, const float* __restrict__ bias,
    __nv_bfloat16* __restrict__ Ch, __nv_bfloat16* __restrict__ Cl, int M, int N, int K)
{
    __shared__ float As[16][128];
    __shared__ float Bs[16][128];
    const int tid = threadIdx.x;
    const int m0 = blockIdx.y * 128;
    const int n0 = blockIdx.x * 128;
    const int ty = tid >> 4;
    const int tx = tid & 15;

    float acc[8][8];
#pragma unroll
    for (int i = 0; i < 8; i++)
#pragma unroll
        for (int j = 0; j < 8; j++) acc[i][j] = 0.f;

    const int arow0 = tid >> 2;
    const int akk   = (tid & 3) * 4;
    const int brow  = tid >> 4;
    const int bcol  = (tid & 15) * 4;

    for (int k0 = 0; k0 < K; k0 += 16) {
#pragma unroll
        for (int p = 0; p < 2; p++) {
            int row = arow0 + p * 64;
            int gmm = m0 + row;
            float4 v = make_float4(0.f, 0.f, 0.f, 0.f);
            if (gmm < M) v = *(const float4*)(A1 + (size_t)gmm * K + k0 + akk);
            As[akk + 0][row] = v.x;
            As[akk + 1][row] = v.y;
            As[akk + 2][row] = v.z;
            As[akk + 3][row] = v.w;
        }
        {
            const float* bp = B + (size_t)(k0 + brow) * N + n0 + bcol;
            float4 v0 = *(const float4*)(bp);
            float4 v1 = *(const float4*)(bp + 64);
            *(float4*)&Bs[brow][bcol]      = v0;
            *(float4*)&Bs[brow][bcol + 64] = v1;
        }
        __syncthreads();
#pragma unroll
        for (int k = 0; k < 16; k++) {
            float ra[8], rb[8];
            *(float4*)&ra[0] = *(const float4*)&As[k][ty * 8];
            *(float4*)&ra[4] = *(const float4*)&As[k][ty * 8 + 4];
            *(float4*)&rb[0] = *(const float4*)&Bs[k][tx * 8];
            *(float4*)&rb[4] = *(const float4*)&Bs[k][tx * 8 + 4];
#pragma unroll
            for (int i = 0; i < 8; i++)
#pragma unroll
                for (int j = 0; j < 8; j++) acc[i][j] += ra[i] * rb[j];
        }
        __syncthreads();
    }

    float bb[8];
    *(float4*)&bb[0] = *(const float4*)(bias + n0 + tx * 8);
    *(float4*)&bb[4] = *(const float4*)(bias + n0 + tx * 8 + 4);
#pragma unroll
    for (int i = 0; i < 8; i++) {
        int gmm = m0 + ty * 8 + i;
        if (gmm >= M) break;
        uint32_t hw[4], lw[4];
#pragma unroll
        for (int j = 0; j < 4; j++) {
            float v0 = fmaxf(acc[i][2 * j] + bb[2 * j], 0.f);
            float v1 = fmaxf(acc[i][2 * j + 1] + bb[2 * j + 1], 0.f);
            split_pair(v0, v1, hw[j], lw[j]);
        }
        *(uint2*)(Ch + (size_t)gmm * N + n0 + tx * 8)     = make_uint2(hw[0], hw[1]);
        *(uint2*)(Ch + (size_t)gmm * N + n0 + tx * 8 + 4) = make_uint2(hw[2], hw[3]);
        *(uint2*)(Cl + (size_t)gmm * N + n0 + tx * 8)     = make_uint2(lw[0], lw[1]);
        *(uint2*)(Cl + (size_t)gmm * N + n0 + tx * 8 + 4) = make_uint2(lw[2], lw[3]);
    }
}

// ---------------- CSR build ----------------
__global__ void count_kernel(const int* __restrict__ dst, int* __restrict__ cnt) {
    int e = blockIdx.x * blockDim.x + threadIdx.x;
    if (e < NE) atomicAdd(&cnt[dst[e]], 1);
}

__global__ __launch_bounds__(1024) void scan_kernel(const int* __restrict__ cnt,
                                                    int* __restrict__ rowptr,
                                                    int* __restrict__ fill) {
    __shared__ int wsum[32];
    __shared__ int s_carry;
    const int tid = threadIdx.x, lane = tid & 31, wid = tid >> 5;
    if (tid == 0) { s_carry = 0; rowptr[0] = 0; }
    __syncthreads();
    for (int base = 0; base < NN; base += 1024) {
        int i = base + tid;
        int v = (i < NN) ? cnt[i] : 0;
        int s = v;
#pragma unroll
        for (int d = 1; d < 32; d <<= 1) {
            int y = __shfl_up_sync(0xffffffffu, s, d);
            if (lane >= d) s += y;
        }
        if (lane == 31) wsum[wid] = s;
        int carry_in = s_carry;
        __syncthreads();
        if (wid == 0) {
            int ws = wsum[lane];
#pragma unroll
            for (int d = 1; d < 32; d <<= 1) {
                int y = __shfl_up_sync(0xffffffffu, ws, d);
                if (lane >= d) ws += y;
            }
            wsum[lane] = ws;
        }
        __syncthreads();
        int off = (wid ? wsum[wid - 1] : 0) + carry_in;
        int inc = s + off;
        if (i < NN) {
            rowptr[i + 1] = inc;
            fill[i] = inc - v;
        }
        __syncthreads();
        if (tid == 1023) s_carry = inc;
        __syncthreads();
    }
}

__global__ void scatter_kernel(const int* __restrict__ src, const int* __restrict__ dst,
                               int* __restrict__ fill, int* __restrict__ col) {
    int e = blockIdx.x * blockDim.x + threadIdx.x;
    if (e < NE) {
        int slot = atomicAdd(&fill[dst[e]], 1);
        col[slot] = src[e];
    }
}

// ---------------- atomic-free aggregation (1 warp / node, hi/lo in, hi/lo out) -------
__device__ __forceinline__ void acc8(float* acc, uint4 hv, uint4 lv) {
    const uint32_t* h = (const uint32_t*)&hv;
    const uint32_t* l = (const uint32_t*)&lv;
#pragma unroll
    for (int p = 0; p < 4; p++) {
        __nv_bfloat162 h2 = *reinterpret_cast<const __nv_bfloat162*>(&h[p]);
        __nv_bfloat162 l2 = *reinterpret_cast<const __nv_bfloat162*>(&l[p]);
        acc[2 * p]     += __low2float(h2)  + __low2float(l2);
        acc[2 * p + 1] += __high2float(h2) + __high2float(l2);
    }
}

__global__ __launch_bounds__(32) void agg_kernel(
    const __nv_bfloat16* __restrict__ th, const __nv_bfloat16* __restrict__ tl,
    const int* __restrict__ rowptr, const int* __restrict__ col,
    __nv_bfloat16* __restrict__ aggh, __nv_bfloat16* __restrict__ aggl)
{
    const int node = blockIdx.x;
    const int tid = threadIdx.x;          // 32 threads x 8 feats = 256
    const int s = rowptr[node];
    const int e = rowptr[node + 1];
    float acc[8];
#pragma unroll
    for (int p = 0; p < 8; p++) acc[p] = 0.f;

    int i = s;
    for (; i + 2 <= e; i += 2) {
        int c0 = __ldg(&col[i]), c1 = __ldg(&col[i + 1]);
        uint4 h0 = *(const uint4*)(th + (size_t)c0 * HID + tid * 8);
        uint4 l0 = *(const uint4*)(tl + (size_t)c0 * HID + tid * 8);
        uint4 h1 = *(const uint4*)(th + (size_t)c1 * HID + tid * 8);
        uint4 l1 = *(const uint4*)(tl + (size_t)c1 * HID + tid * 8);
        acc8(acc, h0, l0);
        acc8(acc, h1, l1);
    }
    if (i < e) {
        int c0 = __ldg(&col[i]);
        uint4 h0 = *(const uint4*)(th + (size_t)c0 * HID + tid * 8);
        uint4 l0 = *(const uint4*)(tl + (size_t)c0 * HID + tid * 8);
        acc8(acc, h0, l0);
    }

    uint32_t hw[4], lw[4];
#pragma unroll
    for (int p = 0; p < 4; p++) split_pair(acc[2 * p], acc[2 * p + 1], hw[p], lw[p]);
    *(uint4*)(aggh + (size_t)node * HID + tid * 8) = *(uint4*)hw;
    *(uint4*)(aggl + (size_t)node * HID + tid * 8) = *(uint4*)lw;
}

// ---------------- output projection: out = tanh(u @ W2 + b2) ----------------
__global__ __launch_bounds__(256) void out_kernel(
    const __nv_bfloat16* __restrict__ uh, const __nv_bfloat16* __restrict__ ul,
    const float* __restrict__ w, const float* __restrict__ b,
    float* __restrict__ out, int M)
{
    __shared__ float ws[256 * 16];
    __shared__ float bs[16];
    const int tid = threadIdx.x;
    for (int i = tid; i < 256 * 16 / 4; i += 256)
        ((float4*)ws)[i] = ((const float4*)w)[i];
    if (tid < 16) bs[tid] = b[tid];
    __syncthreads();

    const int mloc = tid >> 1;
    const int off  = (tid & 1) * 8;
    const int m = blockIdx.x * 128 + mloc;
    if (m >= M) return;

    float acc[8];
#pragma unroll
    for (int j = 0; j < 8; j++) acc[j] = bs[off + j];

    const uint4* ph = (const uint4*)(uh + (size_t)m * HID);
    const uint4* pl = (const uint4*)(ul + (size_t)m * HID);
#pragma unroll 4
    for (int kc = 0; kc < 32; kc++) {
        uint4 hv = ph[kc], lv = pl[kc];
        const uint32_t* hp = (const uint32_t*)&hv;
        const uint32_t* lp = (const uint32_t*)&lv;
        float f[8];
#pragma unroll
        for (int p = 0; p < 4; p++) {
            __nv_bfloat162 h2 = *reinterpret_cast<const __nv_bfloat162*>(&hp[p]);
            __nv_bfloat162 l2 = *reinterpret_cast<const __nv_bfloat162*>(&lp[p]);
            f[2 * p]     = __low2float(h2)  + __low2float(l2);
            f[2 * p + 1] = __high2float(h2) + __high2float(l2);
        }
#pragma unroll
        for (int qv = 0; qv < 8; qv++) {
            const float* wr = &ws[(kc * 8 + qv) * 16 + off];
#pragma unroll
            for (int j = 0; j < 8; j++) acc[j] += f[qv] * wr[j];
        }
    }
    float o[8];
#pragma unroll
    for (int j = 0; j < 8; j++) o[j] = tanhf(acc[j]);
    float* op = out + (size_t)m * 16 + off;
    *(float4*)(op)     = *(float4*)&o[0];
    *(float4*)(op + 4) = *(float4*)&o[4];
}

// ---------------- launcher ----------------
extern "C" void kernel_launch(void* const* d_in, const int* in_sizes, int n_in,
                              void* d_out, int out_size) {
    const float* x       = (const float*)d_in[0];
    const int*   ei      = (const int*)d_in[1];
    const float* pre_w1  = (const float*)d_in[2];
    const float* pre_b1  = (const float*)d_in[3];
    const float* pre_w2  = (const float*)d_in[4];
    const float* pre_b2  = (const float*)d_in[5];
    const float* conv_w  = (const float*)d_in[6];
    const float* conv_b  = (const float*)d_in[7];
    const float* post_w1 = (const float*)d_in[8];
    const float* post_b1 = (const float*)d_in[9];
    const float* post_w2 = (const float*)d_in[10];
    const float* post_b2 = (const float*)d_in[11];
    float* out = (float*)d_out;

    const int* src = ei;
    const int* dst = ei + NE;

    __nv_bfloat16 *ah, *al, *hh, *hl, *th, *tl, *gh, *gl, *uh, *ul;
    int *cnt, *rowptr, *fill, *col;
    __nv_bfloat16 *w2h, *w2l, *wch, *wcl, *wph, *wpl;
    cudaGetSymbolAddress((void**)&ah, g_ah);   cudaGetSymbolAddress((void**)&al, g_al);
    cudaGetSymbolAddress((void**)&hh, g_hh);   cudaGetSymbolAddress((void**)&hl, g_hl);
    cudaGetSymbolAddress((void**)&th, g_th);   cudaGetSymbolAddress((void**)&tl, g_tl);
    cudaGetSymbolAddress((void**)&gh, g_gh);   cudaGetSymbolAddress((void**)&gl, g_gl);
    cudaGetSymbolAddress((void**)&uh, g_uh);   cudaGetSymbolAddress((void**)&ul, g_ul);
    cudaGetSymbolAddress((void**)&cnt, g_cnt);
    cudaGetSymbolAddress((void**)&rowptr, g_rowptr);
    cudaGetSymbolAddress((void**)&fill, g_fill);
    cudaGetSymbolAddress((void**)&col, g_col);
    cudaGetSymbolAddress((void**)&w2h, g_w2h); cudaGetSymbolAddress((void**)&w2l, g_w2l);
    cudaGetSymbolAddress((void**)&wch, g_wch); cudaGetSymbolAddress((void**)&wcl, g_wcl);
    cudaGetSymbolAddress((void**)&wph, g_wph); cudaGetSymbolAddress((void**)&wpl, g_wpl);

    const int DSMEM = 2 * STAGE_B;  // 80 KB
    cudaFuncSetAttribute(mma_gemm<0>, cudaFuncAttributeMaxDynamicSharedMemorySize, DSMEM);
    cudaFuncSetAttribute(mma_gemm<1>, cudaFuncAttributeMaxDynamicSharedMemorySize, DSMEM);

    cudaMemsetAsync(cnt, 0, NN * sizeof(int), 0);

    // weight prep (transpose + bf16 hi/lo split)
    dim3 pb(32, 8);
    prep_kernel<<<dim3(256 / 32, 256 / 32), pb>>>(pre_w2,  w2h, w2l, 256, 256);
    prep_kernel<<<dim3(256 / 32, 256 / 32), pb>>>(conv_w,  wch, wcl, 256, 256);
    prep_kernel<<<dim3(256 / 32, 512 / 32), pb>>>(post_w1, wph, wpl, 512, 256);

    const int MT = (NN + 127) / 128;  // 391
    dim3 gg(2, MT);

    // pre-MLP layer 1 (K=16, fp32 FFMA) -> (ah, al)
    sgemm_pre<<<dim3(2, MT), 256>>>(x, pre_w1, pre_b1, ah, al, NN, HID, 16);
    // pre-MLP layer 2 -> h pair
    mma_gemm<0><<<gg, 256, DSMEM>>>(ah, al, nullptr, nullptr, w2h, w2l, pre_b2,
                                    hh, hl, NN, 256, 256);
    // per-node edge transform -> t pair
    mma_gemm<1><<<gg, 256, DSMEM>>>(hh, hl, nullptr, nullptr, wch, wcl, conv_b,
                                    th, tl, NN, 256, 256);

    // CSR build + atomic-free segment sum
    count_kernel<<<(NE + 255) / 256, 256>>>(dst, cnt);
    scan_kernel<<<1, 1024>>>(cnt, rowptr, fill);
    scatter_kernel<<<(NE + 255) / 256, 256>>>(src, dst, fill, col);
    agg_kernel<<<NN, 32>>>(th, tl, rowptr, col, gh, gl);

    // post-MLP layer 1 (K=512 concat) -> u pair
    mma_gemm<1><<<gg, 256, DSMEM>>>(hh, hl, gh, gl, wph, wpl, post_b1,
                                    uh, ul, NN, 512, 256);
    // output projection + tanh
    out_kernel<<<(NN + 127) / 128, 256>>>(uh, ul, post_w2, post_b2, out, NN);
}

// round 5
// speedup vs baseline: 1.8370x; 1.1494x over previous
#include <cuda_runtime.h>
#include <cuda_bf16.h>
#include <cstdint>
#include <cstddef>

#define NN 50000
#define NE 800000
#define HID 256

// smem stage layout (bytes, pitch 80/row of 32 bf16 + pad):
// Ah[128x80]=10240 | Al=10240 | Bh[128x80]=10240 | Bl=10240
#define STAGE_B 40960

// ---------------- scratch (device globals: no allocation allowed) ----------------
__device__ __nv_bfloat16 g_ah[(size_t)NN * HID], g_al[(size_t)NN * HID];
__device__ __nv_bfloat16 g_th[(size_t)NN * HID], g_tl[(size_t)NN * HID];
__device__ __nv_bfloat16 g_gh[(size_t)NN * HID], g_gl[(size_t)NN * HID];
__device__ __nv_bfloat16 g_uh[(size_t)NN * HID], g_ul[(size_t)NN * HID];
__device__ int g_cnt[NN];
__device__ int g_rowptr[NN + 1];
__device__ int g_fill[NN];
__device__ int g_col[NE];
// composed fp32 weights + biases
__device__ float g_cwt[256 * 256];   // W2 @ conv_w
__device__ float g_cwp[256 * 256];   // W2 @ P1
__device__ float g_cbt[256];         // b2@Wc + conv_b
__device__ float g_cbu[256];         // b2@P1 + post_b1
// split/transposed weights: [N=256][K] bf16, hi+lo
__device__ __nv_bfloat16 g_wth[256 * 256], g_wtl[256 * 256];   // t-GEMM weights
__device__ __nv_bfloat16 g_wuh[256 * 512], g_wul[256 * 512];   // u-GEMM weights (stacked)

// ---------------- helpers ----------------
__device__ __forceinline__ uint32_t s2u(const void* p) {
    uint32_t a;
    asm("{ .reg .u64 t; cvta.to.shared.u64 t, %1; cvt.u32.u64 %0, t; }" : "=r"(a) : "l"(p));
    return a;
}
__device__ __forceinline__ void cp16(uint32_t dst, const void* src, int srcsz) {
    asm volatile("cp.async.cg.shared.global [%0], [%1], 16, %2;"
                 :: "r"(dst), "l"(src), "r"(srcsz) : "memory");
}
#define CP_COMMIT() asm volatile("cp.async.commit_group;" ::: "memory")

__device__ __forceinline__ void ldsm4(uint32_t& r0, uint32_t& r1, uint32_t& r2, uint32_t& r3,
                                      uint32_t addr) {
    asm volatile("ldmatrix.sync.aligned.m8n8.x4.shared.b16 {%0,%1,%2,%3}, [%4];"
                 : "=r"(r0), "=r"(r1), "=r"(r2), "=r"(r3) : "r"(addr));
}

#define MMA_BF16(cc, aa, b0v, b1v)                                              \
    asm volatile(                                                               \
        "mma.sync.aligned.m16n8k16.row.col.f32.bf16.bf16.f32 "                  \
        "{%0,%1,%2,%3}, {%4,%5,%6,%7}, {%8,%9}, {%0,%1,%2,%3};"                 \
        : "+f"(cc[0]), "+f"(cc[1]), "+f"(cc[2]), "+f"(cc[3])                    \
        : "r"(aa[0]), "r"(aa[1]), "r"(aa[2]), "r"(aa[3]), "r"(b0v), "r"(b1v))

__device__ __forceinline__ uint32_t pack_bf16x2(float a, float b) {
    __nv_bfloat162 p = __float22bfloat162_rn(make_float2(a, b));
    return *reinterpret_cast<uint32_t*>(&p);
}
__device__ __forceinline__ void split_pair(float v0, float v1, uint32_t& hw, uint32_t& lw) {
    float h0 = __bfloat162float(__float2bfloat16_rn(v0));
    float h1 = __bfloat162float(__float2bfloat16_rn(v1));
    hw = pack_bf16x2(h0, h1);
    lw = pack_bf16x2(v0 - h0, v1 - h1);
}

// ---------------- weight composition: C[256][256] = A[256][256] @ B[256][256] fp32 ----
__global__ __launch_bounds__(256) void compose_mm(const float* __restrict__ A,
                                                  const float* __restrict__ B,
                                                  float* __restrict__ C) {
    __shared__ float As[16][64];
    __shared__ float Bs[16][64];
    const int t = threadIdx.x;
    const int tx = t & 15, ty = t >> 4;
    const int m0 = blockIdx.y * 64, n0 = blockIdx.x * 64;
    float acc[4][4];
#pragma unroll
    for (int i = 0; i < 4; i++)
#pragma unroll
        for (int j = 0; j < 4; j++) acc[i][j] = 0.f;

    for (int k0 = 0; k0 < 256; k0 += 16) {
#pragma unroll
        for (int i = 0; i < 4; i++) {
            int idx = t + i * 256;
            int r = idx >> 4, c = idx & 15;
            As[c][r] = A[(size_t)(m0 + r) * 256 + k0 + c];
        }
#pragma unroll
        for (int i = 0; i < 4; i++) {
            int idx = t + i * 256;
            int r = idx >> 6, c = idx & 63;
            Bs[r][c] = B[(size_t)(k0 + r) * 256 + n0 + c];
        }
        __syncthreads();
#pragma unroll
        for (int k = 0; k < 16; k++) {
            float ra[4], rb[4];
#pragma unroll
            for (int i = 0; i < 4; i++) ra[i] = As[k][ty * 4 + i];
#pragma unroll
            for (int j = 0; j < 4; j++) rb[j] = Bs[k][tx * 4 + j];
#pragma unroll
            for (int i = 0; i < 4; i++)
#pragma unroll
                for (int j = 0; j < 4; j++) acc[i][j] += ra[i] * rb[j];
        }
        __syncthreads();
    }
#pragma unroll
    for (int i = 0; i < 4; i++)
#pragma unroll
        for (int j = 0; j < 4; j++)
            C[(size_t)(m0 + ty * 4 + i) * 256 + n0 + tx * 4 + j] = acc[i][j];
}

// bout[j] = sum_k b2[k] * W[k][256j] + badd[j]
__global__ __launch_bounds__(256) void compose_bias(const float* __restrict__ b2,
                                                    const float* __restrict__ W,
                                                    const float* __restrict__ badd,
                                                    float* __restrict__ bout) {
    int j = threadIdx.x;
    float acc = badd[j];
    for (int k = 0; k < 256; k++) acc += b2[k] * W[(size_t)k * 256 + j];
    bout[j] = acc;
}

// ---------------- prep: W[Krows][256] fp32 -> hi/lo [N=256][kpitch] at koff ----------
__global__ void prep2(const float* __restrict__ W, __nv_bfloat16* __restrict__ hi,
                      __nv_bfloat16* __restrict__ lo, int kpitch, int koff) {
    __shared__ float tile[32][33];
    int k0 = blockIdx.y * 32, n0 = blockIdx.x * 32;
    int tx = threadIdx.x, ty = threadIdx.y;  // 32 x 8
    for (int i = ty; i < 32; i += 8) tile[i][tx] = W[(size_t)(k0 + i) * 256 + n0 + tx];
    __syncthreads();
    for (int i = ty; i < 32; i += 8) {
        float v = tile[tx][i];  // = W[k0+tx][n0+i]
        __nv_bfloat16 h = __float2bfloat16_rn(v);
        hi[(size_t)(n0 + i) * kpitch + koff + k0 + tx] = h;
        lo[(size_t)(n0 + i) * kpitch + koff + k0 + tx] =
            __float2bfloat16_rn(v - __bfloat162float(h));
    }
}

// ---------------- pre-MLP layer 1: a = relu(x@w1+b1), K=16, hi/lo out ---------------
__global__ __launch_bounds__(256) void pre_kernel(
    const float* __restrict__ x, const float* __restrict__ w1, const float* __restrict__ b1,
    __nv_bfloat16* __restrict__ Ch, __nv_bfloat16* __restrict__ Cl)
{
    __shared__ float ws[16 * 256];
    __shared__ float bs[256];
    const int tid = threadIdx.x;
    for (int i = tid; i < 1024; i += 256) ((float4*)ws)[i] = ((const float4*)w1)[i];
    bs[tid] = b1[tid];
    __syncthreads();

    const int warp = tid >> 5, lane = tid & 31;
#pragma unroll
    for (int r = 0; r < 4; r++) {
        int row = blockIdx.x * 32 + warp * 4 + r;
        if (row >= NN) break;
        float xv[16];
        const float4* xp = (const float4*)(x + (size_t)row * 16);
#pragma unroll
        for (int q = 0; q < 4; q++) *(float4*)&xv[q * 4] = xp[q];
        float acc[8];
#pragma unroll
        for (int j = 0; j < 8; j++) acc[j] = bs[lane + 32 * j];
#pragma unroll
        for (int k = 0; k < 16; k++) {
            float xk = xv[k];
            const float* wr = &ws[k * 256 + lane];
#pragma unroll
            for (int j = 0; j < 8; j++) acc[j] += xk * wr[32 * j];
        }
#pragma unroll
        for (int j = 0; j < 8; j++) {
            float v = fmaxf(acc[j], 0.f);
            __nv_bfloat16 h = __float2bfloat16_rn(v);
            Ch[(size_t)row * 256 + lane + 32 * j] = h;
            Cl[(size_t)row * 256 + lane + 32 * j] =
                __float2bfloat16_rn(v - __bfloat162float(h));
        }
    }
}

// ---------------- tensor-core GEMM: C(hi/lo) = act(concat(A1,A2) @ W + bias) ----------
template <int ACT>
__global__ __launch_bounds__(256, 2) void mma_gemm(
    const __nv_bfloat16* __restrict__ A1h, const __nv_bfloat16* __restrict__ A1l,
    const __nv_bfloat16* __restrict__ A2h, const __nv_bfloat16* __restrict__ A2l,
    const __nv_bfloat16* __restrict__ Wh,  const __nv_bfloat16* __restrict__ Wl,
    const float* __restrict__ bias,
    __nv_bfloat16* __restrict__ Ch, __nv_bfloat16* __restrict__ Cl,
    int M, int K, int K1)
{
    extern __shared__ char smc[];
    __shared__ float sbias[128];

    const int tid = threadIdx.x;
    const int wid = tid >> 5, lane = tid & 31;
    const int g = lane >> 2, tg = lane & 3;
    const int wm = wid >> 1, wn = wid & 1;
    const int m0 = blockIdx.y * 128, n0 = blockIdx.x * 128;
    const uint32_t smc_u = s2u(smc);

    if (tid < 128) sbias[tid] = bias[n0 + tid];

    const int arow = tid >> 1;
    const int aks  = (tid & 1) * 16;
    const int gm   = m0 + arow;
    const int okA  = (gm < M) ? 16 : 0;

    const int q = lane >> 3, rr = lane & 7;
    const uint32_t aoff0 = (uint32_t)((wm * 32 + (q & 1) * 8 + rr) * 80 + (q >> 1) * 16);
    const uint32_t boff0 = (uint32_t)(20480 + (wn * 64 + (q >> 1) * 8 + rr) * 80 + (q & 1) * 16);

    float acc[2][8][4];
#pragma unroll
    for (int i = 0; i < 2; i++)
#pragma unroll
        for (int j = 0; j < 8; j++)
#pragma unroll
            for (int p = 0; p < 4; p++) acc[i][j][p] = 0.f;

    const int NC = K >> 5;

    auto STAGE = [&](int c) {
        const int ck = c * 32;
        const __nv_bfloat16 *Ah, *Al; int lda, kof;
        if (ck < K1) { Ah = A1h; Al = A1l; lda = K1;     kof = ck; }
        else         { Ah = A2h; Al = A2l; lda = K - K1; kof = ck - K1; }
        const uint32_t sb = smc_u + (uint32_t)((c & 1) * STAGE_B);
        const uint32_t da = sb + (uint32_t)(arow * 80 + (tid & 1) * 32);
        const __nv_bfloat16* pah = Ah + (size_t)gm * lda + kof + aks;
        const __nv_bfloat16* pal = Al + (size_t)gm * lda + kof + aks;
        cp16(da, pah, okA);               cp16(da + 16, pah + 8, okA);
        cp16(da + 10240, pal, okA);       cp16(da + 10240 + 16, pal + 8, okA);
        const __nv_bfloat16* pbh = Wh + (size_t)(n0 + arow) * K + ck + aks;
        const __nv_bfloat16* pbl = Wl + (size_t)(n0 + arow) * K + ck + aks;
        cp16(da + 20480, pbh, 16);        cp16(da + 20480 + 16, pbh + 8, 16);
        cp16(da + 30720, pbl, 16);        cp16(da + 30720 + 16, pbl + 8, 16);
        CP_COMMIT();
    };

    STAGE(0);

    for (int c = 0; c < NC; c++) {
        if (c + 1 < NC) {
            STAGE(c + 1);
            asm volatile("cp.async.wait_group 1;" ::: "memory");
        } else {
            asm volatile("cp.async.wait_group 0;" ::: "memory");
        }
        __syncthreads();

        const uint32_t sb = smc_u + (uint32_t)((c & 1) * STAGE_B);
#pragma unroll
        for (int ks = 0; ks < 2; ks++) {
            const uint32_t ko = (uint32_t)(ks * 32);
            uint32_t ah[2][4], bb[8][2];
            ldsm4(ah[0][0], ah[0][1], ah[0][2], ah[0][3], sb + aoff0 + ko);
            ldsm4(ah[1][0], ah[1][1], ah[1][2], ah[1][3], sb + aoff0 + 1280 + ko);
#pragma unroll
            for (int jp = 0; jp < 4; jp++)
                ldsm4(bb[2 * jp][0], bb[2 * jp][1], bb[2 * jp + 1][0], bb[2 * jp + 1][1],
                      sb + boff0 + (uint32_t)(jp * 1280) + ko);
#pragma unroll
            for (int i = 0; i < 2; i++)
#pragma unroll
                for (int j = 0; j < 8; j++) MMA_BF16(acc[i][j], ah[i], bb[j][0], bb[j][1]);

            uint32_t al[2][4];
            ldsm4(al[0][0], al[0][1], al[0][2], al[0][3], sb + 10240 + aoff0 + ko);
            ldsm4(al[1][0], al[1][1], al[1][2], al[1][3], sb + 10240 + aoff0 + 1280 + ko);
#pragma unroll
            for (int i = 0; i < 2; i++)
#pragma unroll
                for (int j = 0; j < 8; j++) MMA_BF16(acc[i][j], al[i], bb[j][0], bb[j][1]);

#pragma unroll
            for (int jp = 0; jp < 4; jp++)
                ldsm4(bb[2 * jp][0], bb[2 * jp][1], bb[2 * jp + 1][0], bb[2 * jp + 1][1],
                      sb + 10240 + boff0 + (uint32_t)(jp * 1280) + ko);
#pragma unroll
            for (int i = 0; i < 2; i++)
#pragma unroll
                for (int j = 0; j < 8; j++) MMA_BF16(acc[i][j], ah[i], bb[j][0], bb[j][1]);
        }
        __syncthreads();
    }

    // epilogue: bias + activation + hi/lo split store
#pragma unroll
    for (int i = 0; i < 2; i++) {
        int r0 = m0 + wm * 32 + i * 16 + g;
#pragma unroll
        for (int j = 0; j < 8; j++) {
            int cl = wn * 64 + j * 8 + tg * 2;
            float b0 = sbias[cl], b1 = sbias[cl + 1];
            float v0 = acc[i][j][0] + b0, v1 = acc[i][j][1] + b1;
            float v2 = acc[i][j][2] + b0, v3 = acc[i][j][3] + b1;
            if (ACT == 1) {
                v0 = fmaxf(v0, 0.f); v1 = fmaxf(v1, 0.f);
                v2 = fmaxf(v2, 0.f); v3 = fmaxf(v3, 0.f);
            }
            uint32_t hw, lw;
            if (r0 < M) {
                split_pair(v0, v1, hw, lw);
                *(uint32_t*)(Ch + (size_t)r0 * 256 + n0 + cl) = hw;
                *(uint32_t*)(Cl + (size_t)r0 * 256 + n0 + cl) = lw;
            }
            if (r0 + 8 < M) {
                split_pair(v2, v3, hw, lw);
                *(uint32_t*)(Ch + (size_t)(r0 + 8) * 256 + n0 + cl) = hw;
                *(uint32_t*)(Cl + (size_t)(r0 + 8) * 256 + n0 + cl) = lw;
            }
        }
    }
}

// ---------------- CSR build ----------------
__global__ void count_kernel(const int* __restrict__ dst, int* __restrict__ cnt) {
    int e = blockIdx.x * blockDim.x + threadIdx.x;
    if (e < NE) atomicAdd(&cnt[dst[e]], 1);
}

__global__ __launch_bounds__(1024) void scan_kernel(const int* __restrict__ cnt,
                                                    int* __restrict__ rowptr,
                                                    int* __restrict__ fill) {
    __shared__ int wsum[32];
    __shared__ int s_carry;
    const int tid = threadIdx.x, lane = tid & 31, wid = tid >> 5;
    if (tid == 0) { s_carry = 0; rowptr[0] = 0; }
    __syncthreads();
    for (int base = 0; base < NN; base += 1024) {
        int i = base + tid;
        int v = (i < NN) ? cnt[i] : 0;
        int s = v;
#pragma unroll
        for (int d = 1; d < 32; d <<= 1) {
            int y = __shfl_up_sync(0xffffffffu, s, d);
            if (lane >= d) s += y;
        }
        if (lane == 31) wsum[wid] = s;
        int carry_in = s_carry;
        __syncthreads();
        if (wid == 0) {
            int ws = wsum[lane];
#pragma unroll
            for (int d = 1; d < 32; d <<= 1) {
                int y = __shfl_up_sync(0xffffffffu, ws, d);
                if (lane >= d) ws += y;
            }
            wsum[lane] = ws;
        }
        __syncthreads();
        int off = (wid ? wsum[wid - 1] : 0) + carry_in;
        int inc = s + off;
        if (i < NN) {
            rowptr[i + 1] = inc;
            fill[i] = inc - v;
        }
        __syncthreads();
        if (tid == 1023) s_carry = inc;
        __syncthreads();
    }
}

__global__ void scatter_kernel(const int* __restrict__ src, const int* __restrict__ dst,
                               int* __restrict__ fill, int* __restrict__ col) {
    int e = blockIdx.x * blockDim.x + threadIdx.x;
    if (e < NE) {
        int slot = atomicAdd(&fill[dst[e]], 1);
        col[slot] = src[e];
    }
}

// ---------------- atomic-free aggregation (1 warp / node, hi/lo in, hi/lo out) -------
__device__ __forceinline__ void acc8(float* acc, uint4 hv, uint4 lv) {
    const uint32_t* h = (const uint32_t*)&hv;
    const uint32_t* l = (const uint32_t*)&lv;
#pragma unroll
    for (int p = 0; p < 4; p++) {
        __nv_bfloat162 h2 = *reinterpret_cast<const __nv_bfloat162*>(&h[p]);
        __nv_bfloat162 l2 = *reinterpret_cast<const __nv_bfloat162*>(&l[p]);
        acc[2 * p]     += __low2float(h2)  + __low2float(l2);
        acc[2 * p + 1] += __high2float(h2) + __high2float(l2);
    }
}

__global__ __launch_bounds__(32) void agg_kernel(
    const __nv_bfloat16* __restrict__ th, const __nv_bfloat16* __restrict__ tl,
    const int* __restrict__ rowptr, const int* __restrict__ col,
    __nv_bfloat16* __restrict__ aggh, __nv_bfloat16* __restrict__ aggl)
{
    const int node = blockIdx.x;
    const int tid = threadIdx.x;
    const int s = rowptr[node];
    const int e = rowptr[node + 1];
    float acc[8];
#pragma unroll
    for (int p = 0; p < 8; p++) acc[p] = 0.f;

    int i = s;
    for (; i + 4 <= e; i += 4) {
        int c0 = __ldg(&col[i]),     c1 = __ldg(&col[i + 1]);
        int c2 = __ldg(&col[i + 2]), c3 = __ldg(&col[i + 3]);
        uint4 h0 = *(const uint4*)(th + (size_t)c0 * HID + tid * 8);
        uint4 l0 = *(const uint4*)(tl + (size_t)c0 * HID + tid * 8);
        uint4 h1 = *(const uint4*)(th + (size_t)c1 * HID + tid * 8);
        uint4 l1 = *(const uint4*)(tl + (size_t)c1 * HID + tid * 8);
        uint4 h2 = *(const uint4*)(th + (size_t)c2 * HID + tid * 8);
        uint4 l2 = *(const uint4*)(tl + (size_t)c2 * HID + tid * 8);
        uint4 h3 = *(const uint4*)(th + (size_t)c3 * HID + tid * 8);
        uint4 l3 = *(const uint4*)(tl + (size_t)c3 * HID + tid * 8);
        acc8(acc, h0, l0); acc8(acc, h1, l1);
        acc8(acc, h2, l2); acc8(acc, h3, l3);
    }
    for (; i < e; i++) {
        int c0 = __ldg(&col[i]);
        uint4 h0 = *(const uint4*)(th + (size_t)c0 * HID + tid * 8);
        uint4 l0 = *(const uint4*)(tl + (size_t)c0 * HID + tid * 8);
        acc8(acc, h0, l0);
    }

    uint32_t hw[4], lw[4];
#pragma unroll
    for (int p = 0; p < 4; p++) split_pair(acc[2 * p], acc[2 * p + 1], hw[p], lw[p]);
    *(uint4*)(aggh + (size_t)node * HID + tid * 8) = *(uint4*)hw;
    *(uint4*)(aggl + (size_t)node * HID + tid * 8) = *(uint4*)lw;
}

// ---------------- output projection: out = tanh(u @ W2 + b2) ----------------
__global__ __launch_bounds__(256) void out_kernel(
    const __nv_bfloat16* __restrict__ uh, const __nv_bfloat16* __restrict__ ul,
    const float* __restrict__ w, const float* __restrict__ b,
    float* __restrict__ out, int M)
{
    __shared__ float ws[256 * 16];
    __shared__ float bs[16];
    const int tid = threadIdx.x;
    for (int i = tid; i < 256 * 16 / 4; i += 256)
        ((float4*)ws)[i] = ((const float4*)w)[i];
    if (tid < 16) bs[tid] = b[tid];
    __syncthreads();

    const int mloc = tid >> 1;
    const int off  = (tid & 1) * 8;
    const int m = blockIdx.x * 128 + mloc;
    if (m >= M) return;

    float acc[8];
#pragma unroll
    for (int j = 0; j < 8; j++) acc[j] = bs[off + j];

    const uint4* ph = (const uint4*)(uh + (size_t)m * HID);
    const uint4* pl = (const uint4*)(ul + (size_t)m * HID);
#pragma unroll 4
    for (int kc = 0; kc < 32; kc++) {
        uint4 hv = ph[kc], lv = pl[kc];
        const uint32_t* hp = (const uint32_t*)&hv;
        const uint32_t* lp = (const uint32_t*)&lv;
        float f[8];
#pragma unroll
        for (int p = 0; p < 4; p++) {
            __nv_bfloat162 h2 = *reinterpret_cast<const __nv_bfloat162*>(&hp[p]);
            __nv_bfloat162 l2 = *reinterpret_cast<const __nv_bfloat162*>(&lp[p]);
            f[2 * p]     = __low2float(h2)  + __low2float(l2);
            f[2 * p + 1] = __high2float(h2) + __high2float(l2);
        }
#pragma unroll
        for (int qv = 0; qv < 8; qv++) {
            const float* wr = &ws[(kc * 8 + qv) * 16 + off];
#pragma unroll
            for (int j = 0; j < 8; j++) acc[j] += f[qv] * wr[j];
        }
    }
    float o[8];
#pragma unroll
    for (int j = 0; j < 8; j++) o[j] = tanhf(acc[j]);
    float* op = out + (size_t)m * 16 + off;
    *(float4*)(op)     = *(float4*)&o[0];
    *(float4*)(op + 4) = *(float4*)&o[4];
}

// ---------------- launcher ----------------
extern "C" void kernel_launch(void* const* d_in, const int* in_sizes, int n_in,
                              void* d_out, int out_size) {
    const float* x       = (const float*)d_in[0];
    const int*   ei      = (const int*)d_in[1];
    const float* pre_w1  = (const float*)d_in[2];
    const float* pre_b1  = (const float*)d_in[3];
    const float* pre_w2  = (const float*)d_in[4];
    const float* pre_b2  = (const float*)d_in[5];
    const float* conv_w  = (const float*)d_in[6];
    const float* conv_b  = (const float*)d_in[7];
    const float* post_w1 = (const float*)d_in[8];
    const float* post_b1 = (const float*)d_in[9];
    const float* post_w2 = (const float*)d_in[10];
    const float* post_b2 = (const float*)d_in[11];
    float* out = (float*)d_out;

    const int* src = ei;
    const int* dst = ei + NE;

    __nv_bfloat16 *ah, *al, *th, *tl, *gh, *gl, *uh, *ul;
    int *cnt, *rowptr, *fill, *col;
    float *cwt, *cwp, *cbt, *cbu;
    __nv_bfloat16 *wth, *wtl, *wuh, *wul;
    cudaGetSymbolAddress((void**)&ah, g_ah);   cudaGetSymbolAddress((void**)&al, g_al);
    cudaGetSymbolAddress((void**)&th, g_th);   cudaGetSymbolAddress((void**)&tl, g_tl);
    cudaGetSymbolAddress((void**)&gh, g_gh);   cudaGetSymbolAddress((void**)&gl, g_gl);
    cudaGetSymbolAddress((void**)&uh, g_uh);   cudaGetSymbolAddress((void**)&ul, g_ul);
    cudaGetSymbolAddress((void**)&cnt, g_cnt);
    cudaGetSymbolAddress((void**)&rowptr, g_rowptr);
    cudaGetSymbolAddress((void**)&fill, g_fill);
    cudaGetSymbolAddress((void**)&col, g_col);
    cudaGetSymbolAddress((void**)&cwt, g_cwt); cudaGetSymbolAddress((void**)&cwp, g_cwp);
    cudaGetSymbolAddress((void**)&cbt, g_cbt); cudaGetSymbolAddress((void**)&cbu, g_cbu);
    cudaGetSymbolAddress((void**)&wth, g_wth); cudaGetSymbolAddress((void**)&wtl, g_wtl);
    cudaGetSymbolAddress((void**)&wuh, g_wuh); cudaGetSymbolAddress((void**)&wul, g_wul);

    const float* P1 = post_w1;                 // rows 0..255 of [512][256]
    const float* P2 = post_w1 + 256 * 256;     // rows 256..511

    const int DSMEM = 2 * STAGE_B;  // 80 KB
    cudaFuncSetAttribute(mma_gemm<1>, cudaFuncAttributeMaxDynamicSharedMemorySize, DSMEM);

    cudaMemsetAsync(cnt, 0, NN * sizeof(int), 0);

    // ---- weight composition (h folded away): Wt = W2@Wc, Wp = W2@P1 ----
    compose_mm<<<dim3(4, 4), 256>>>(pre_w2, conv_w, cwt);
    compose_mm<<<dim3(4, 4), 256>>>(pre_w2, P1, cwp);
    compose_bias<<<1, 256>>>(pre_b2, conv_w, conv_b, cbt);
    compose_bias<<<1, 256>>>(pre_b2, P1, post_b1, cbu);

    // ---- transpose + bf16 hi/lo split ----
    dim3 pb(32, 8);
    prep2<<<dim3(8, 8),  pb>>>(cwt, wth, wtl, 256, 0);    // t weights [256][256]
    prep2<<<dim3(8, 8),  pb>>>(cwp, wuh, wul, 512, 0);    // u weights, a-part
    prep2<<<dim3(8, 8),  pb>>>(P2,  wuh, wul, 512, 256);  // u weights, agg-part

    // ---- pre-MLP layer 1 -> a pair ----
    pre_kernel<<<(NN + 31) / 32, 256>>>(x, pre_w1, pre_b1, ah, al);

    const int MT = (NN + 127) / 128;  // 391
    dim3 gg(2, MT);

    // ---- t = relu(a@Wt + bt) ----
    mma_gemm<1><<<gg, 256, DSMEM>>>(ah, al, nullptr, nullptr, wth, wtl, cbt,
                                    th, tl, NN, 256, 256);

    // ---- CSR build + atomic-free segment sum ----
    count_kernel<<<(NE + 255) / 256, 256>>>(dst, cnt);
    scan_kernel<<<1, 1024>>>(cnt, rowptr, fill);
    scatter_kernel<<<(NE + 255) / 256, 256>>>(src, dst, fill, col);
    agg_kernel<<<NN, 32>>>(th, tl, rowptr, col, gh, gl);

    // ---- u = relu(a@Wp + agg@P2 + bu)  (K=512 concat) ----
    mma_gemm<1><<<gg, 256, DSMEM>>>(ah, al, gh, gl, wuh, wul, cbu,
                                    uh, ul, NN, 512, 256);
    // ---- out = tanh(u@post_w2 + post_b2) ----
    out_kernel<<<(NN + 127) / 128, 256>>>(uh, ul, post_w2, post_b2, out, NN);
}

// round 6
// speedup vs baseline: 1.8730x; 1.0196x over previous
#include <cuda_runtime.h>
#include <cuda_bf16.h>
#include <cstdint>
#include <cstddef>

#define NN 50000
#define NE 800000
#define HID 256

// smem stage layout (bytes, pitch 80/row of 32 bf16 + pad):
// Ah[128x80]=10240 | Al=10240 | Bh[128x80]=10240 | Bl=10240
#define STAGE_B 40960

// ---------------- scratch (device globals: no allocation allowed) ----------------
__device__ __nv_bfloat16 g_ah[(size_t)NN * HID], g_al[(size_t)NN * HID];
__device__ __nv_bfloat16 g_th[(size_t)NN * HID], g_tl[(size_t)NN * HID];
__device__ __nv_bfloat16 g_gh[(size_t)NN * HID], g_gl[(size_t)NN * HID];
__device__ __nv_bfloat16 g_uh[(size_t)NN * HID], g_ul[(size_t)NN * HID];
__device__ int g_cnt[NN];
__device__ int g_rowptr[NN + 1];
__device__ int g_fill[NN];
__device__ int g_col[NE];
// bias composition partials + composed biases
__device__ float g_bpart[2 * 8 * 256];
__device__ float g_cbt[256];         // b2@Wc + conv_b
__device__ float g_cbu[256];         // b2@P1 + post_b1
// split/transposed weights: [N=256][K] bf16, hi+lo
__device__ __nv_bfloat16 g_wth[256 * 256], g_wtl[256 * 256];   // t-GEMM weights
__device__ __nv_bfloat16 g_wuh[256 * 512], g_wul[256 * 512];   // u-GEMM weights (stacked)

// ---------------- helpers ----------------
__device__ __forceinline__ uint32_t s2u(const void* p) {
    uint32_t a;
    asm("{ .reg .u64 t; cvta.to.shared.u64 t, %1; cvt.u32.u64 %0, t; }" : "=r"(a) : "l"(p));
    return a;
}
__device__ __forceinline__ void cp16(uint32_t dst, const void* src, int srcsz) {
    asm volatile("cp.async.cg.shared.global [%0], [%1], 16, %2;"
                 :: "r"(dst), "l"(src), "r"(srcsz) : "memory");
}
#define CP_COMMIT() asm volatile("cp.async.commit_group;" ::: "memory")

__device__ __forceinline__ void ldsm4(uint32_t& r0, uint32_t& r1, uint32_t& r2, uint32_t& r3,
                                      uint32_t addr) {
    asm volatile("ldmatrix.sync.aligned.m8n8.x4.shared.b16 {%0,%1,%2,%3}, [%4];"
                 : "=r"(r0), "=r"(r1), "=r"(r2), "=r"(r3) : "r"(addr));
}

#define MMA_BF16(cc, aa, b0v, b1v)                                              \
    asm volatile(                                                               \
        "mma.sync.aligned.m16n8k16.row.col.f32.bf16.bf16.f32 "                  \
        "{%0,%1,%2,%3}, {%4,%5,%6,%7}, {%8,%9}, {%0,%1,%2,%3};"                 \
        : "+f"(cc[0]), "+f"(cc[1]), "+f"(cc[2]), "+f"(cc[3])                    \
        : "r"(aa[0]), "r"(aa[1]), "r"(aa[2]), "r"(aa[3]), "r"(b0v), "r"(b1v))

__device__ __forceinline__ uint32_t pack_bf16x2(float a, float b) {
    __nv_bfloat162 p = __float22bfloat162_rn(make_float2(a, b));
    return *reinterpret_cast<uint32_t*>(&p);
}
__device__ __forceinline__ void split_pair(float v0, float v1, uint32_t& hw, uint32_t& lw) {
    float h0 = __bfloat162float(__float2bfloat16_rn(v0));
    float h1 = __bfloat162float(__float2bfloat16_rn(v1));
    hw = pack_bf16x2(h0, h1);
    lw = pack_bf16x2(v0 - h0, v1 - h1);
}

// ---------------- fused compose+prep: hi/lo[n][koff+k] = split((A@B)[k][n]) ----------
__global__ __launch_bounds__(256) void compose_prep(
    const float* __restrict__ A, const float* __restrict__ B,
    __nv_bfloat16* __restrict__ hi, __nv_bfloat16* __restrict__ lo,
    int kpitch, int koff)
{
    __shared__ float As[16][64];
    __shared__ float Bs[16][64];
    const int t = threadIdx.x;
    const int tx = t & 15, ty = t >> 4;
    const int m0 = blockIdx.y * 64, n0 = blockIdx.x * 64;
    float acc[4][4];
#pragma unroll
    for (int i = 0; i < 4; i++)
#pragma unroll
        for (int j = 0; j < 4; j++) acc[i][j] = 0.f;

    for (int k0 = 0; k0 < 256; k0 += 16) {
#pragma unroll
        for (int i = 0; i < 4; i++) {
            int idx = t + i * 256;
            int r = idx >> 4, c = idx & 15;
            As[c][r] = A[(size_t)(m0 + r) * 256 + k0 + c];
        }
#pragma unroll
        for (int i = 0; i < 4; i++) {
            int idx = t + i * 256;
            int r = idx >> 6, c = idx & 63;
            Bs[r][c] = B[(size_t)(k0 + r) * 256 + n0 + c];
        }
        __syncthreads();
#pragma unroll
        for (int k = 0; k < 16; k++) {
            float ra[4], rb[4];
#pragma unroll
            for (int i = 0; i < 4; i++) ra[i] = As[k][ty * 4 + i];
#pragma unroll
            for (int j = 0; j < 4; j++) rb[j] = Bs[k][tx * 4 + j];
#pragma unroll
            for (int i = 0; i < 4; i++)
#pragma unroll
                for (int j = 0; j < 4; j++) acc[i][j] += ra[i] * rb[j];
        }
        __syncthreads();
    }
    // emit transposed hi/lo: C[k=m][n] -> W[n][koff+m]
#pragma unroll
    for (int i = 0; i < 4; i++) {
        int kk = m0 + ty * 4 + i;
#pragma unroll
        for (int j = 0; j < 4; j++) {
            int nn = n0 + tx * 4 + j;
            float v = acc[i][j];
            __nv_bfloat16 h = __float2bfloat16_rn(v);
            hi[(size_t)nn * kpitch + koff + kk] = h;
            lo[(size_t)nn * kpitch + koff + kk] =
                __float2bfloat16_rn(v - __bfloat162float(h));
        }
    }
}

// ---------------- prep (transpose + split only, for P2) ----------------
__global__ void prep2(const float* __restrict__ W, __nv_bfloat16* __restrict__ hi,
                      __nv_bfloat16* __restrict__ lo, int kpitch, int koff) {
    __shared__ float tile[32][33];
    int k0 = blockIdx.y * 32, n0 = blockIdx.x * 32;
    int tx = threadIdx.x, ty = threadIdx.y;  // 32 x 8
    for (int i = ty; i < 32; i += 8) tile[i][tx] = W[(size_t)(k0 + i) * 256 + n0 + tx];
    __syncthreads();
    for (int i = ty; i < 32; i += 8) {
        float v = tile[tx][i];  // = W[k0+tx][n0+i]
        __nv_bfloat16 h = __float2bfloat16_rn(v);
        hi[(size_t)(n0 + i) * kpitch + koff + k0 + tx] = h;
        lo[(size_t)(n0 + i) * kpitch + koff + k0 + tx] =
            __float2bfloat16_rn(v - __bfloat162float(h));
    }
}

// ---------------- bias composition: bout = b2 @ W + badd (2-stage, deterministic) ----
// grid (8, 2): blockIdx.y selects which (W, badd, bout) set; 8 k-chunks of 32.
__global__ __launch_bounds__(256) void bias_part(
    const float* __restrict__ b2,
    const float* __restrict__ W0, const float* __restrict__ W1,
    float* __restrict__ part)
{
    const float* W = blockIdx.y ? W1 : W0;
    int b = blockIdx.x, j = threadIdx.x;
    float acc = 0.f;
#pragma unroll 8
    for (int k = b * 32; k < b * 32 + 32; k++) acc += b2[k] * W[(size_t)k * 256 + j];
    part[(size_t)blockIdx.y * 2048 + b * 256 + j] = acc;
}
__global__ __launch_bounds__(256) void bias_fin(
    const float* __restrict__ part,
    const float* __restrict__ badd0, const float* __restrict__ badd1,
    float* __restrict__ bout0, float* __restrict__ bout1)
{
    int j = threadIdx.x;
    const float* badd = blockIdx.y ? badd1 : badd0;
    float* bout = blockIdx.y ? bout1 : bout0;
    float acc = badd[j];
#pragma unroll
    for (int b = 0; b < 8; b++) acc += part[(size_t)blockIdx.y * 2048 + b * 256 + j];
    bout[j] = acc;
}

// ---------------- pre-MLP layer 1: a = relu(x@w1+b1), K=16, hi/lo out ---------------
__global__ __launch_bounds__(256) void pre_kernel(
    const float* __restrict__ x, const float* __restrict__ w1, const float* __restrict__ b1,
    __nv_bfloat16* __restrict__ Ch, __nv_bfloat16* __restrict__ Cl)
{
    __shared__ float ws[16 * 256];
    __shared__ float bs[256];
    const int tid = threadIdx.x;
    for (int i = tid; i < 1024; i += 256) ((float4*)ws)[i] = ((const float4*)w1)[i];
    bs[tid] = b1[tid];
    __syncthreads();

    const int warp = tid >> 5, lane = tid & 31;
#pragma unroll
    for (int r = 0; r < 4; r++) {
        int row = blockIdx.x * 32 + warp * 4 + r;
        if (row >= NN) break;
        float xv[16];
        const float4* xp = (const float4*)(x + (size_t)row * 16);
#pragma unroll
        for (int q = 0; q < 4; q++) *(float4*)&xv[q * 4] = xp[q];
        float acc[8];
#pragma unroll
        for (int j = 0; j < 8; j++) acc[j] = bs[lane + 32 * j];
#pragma unroll
        for (int k = 0; k < 16; k++) {
            float xk = xv[k];
            const float* wr = &ws[k * 256 + lane];
#pragma unroll
            for (int j = 0; j < 8; j++) acc[j] += xk * wr[32 * j];
        }
#pragma unroll
        for (int j = 0; j < 8; j++) {
            float v = fmaxf(acc[j], 0.f);
            __nv_bfloat16 h = __float2bfloat16_rn(v);
            Ch[(size_t)row * 256 + lane + 32 * j] = h;
            Cl[(size_t)row * 256 + lane + 32 * j] =
                __float2bfloat16_rn(v - __bfloat162float(h));
        }
    }
}

// ---------------- tensor-core GEMM: C(hi/lo) = act(concat(A1,A2) @ W + bias) ----------
template <int ACT>
__global__ __launch_bounds__(256, 2) void mma_gemm(
    const __nv_bfloat16* __restrict__ A1h, const __nv_bfloat16* __restrict__ A1l,
    const __nv_bfloat16* __restrict__ A2h, const __nv_bfloat16* __restrict__ A2l,
    const __nv_bfloat16* __restrict__ Wh,  const __nv_bfloat16* __restrict__ Wl,
    const float* __restrict__ bias,
    __nv_bfloat16* __restrict__ Ch, __nv_bfloat16* __restrict__ Cl,
    int M, int K, int K1)
{
    extern __shared__ char smc[];
    __shared__ float sbias[128];

    const int tid = threadIdx.x;
    const int wid = tid >> 5, lane = tid & 31;
    const int g = lane >> 2, tg = lane & 3;
    const int wm = wid >> 1, wn = wid & 1;
    const int m0 = blockIdx.y * 128, n0 = blockIdx.x * 128;
    const uint32_t smc_u = s2u(smc);

    if (tid < 128) sbias[tid] = bias[n0 + tid];

    const int arow = tid >> 1;
    const int aks  = (tid & 1) * 16;
    const int gm   = m0 + arow;
    const int okA  = (gm < M) ? 16 : 0;

    const int q = lane >> 3, rr = lane & 7;
    const uint32_t aoff0 = (uint32_t)((wm * 32 + (q & 1) * 8 + rr) * 80 + (q >> 1) * 16);
    const uint32_t boff0 = (uint32_t)(20480 + (wn * 64 + (q >> 1) * 8 + rr) * 80 + (q & 1) * 16);

    float acc[2][8][4];
#pragma unroll
    for (int i = 0; i < 2; i++)
#pragma unroll
        for (int j = 0; j < 8; j++)
#pragma unroll
            for (int p = 0; p < 4; p++) acc[i][j][p] = 0.f;

    const int NC = K >> 5;

    auto STAGE = [&](int c) {
        const int ck = c * 32;
        const __nv_bfloat16 *Ah, *Al; int lda, kof;
        if (ck < K1) { Ah = A1h; Al = A1l; lda = K1;     kof = ck; }
        else         { Ah = A2h; Al = A2l; lda = K - K1; kof = ck - K1; }
        const uint32_t sb = smc_u + (uint32_t)((c & 1) * STAGE_B);
        const uint32_t da = sb + (uint32_t)(arow * 80 + (tid & 1) * 32);
        const __nv_bfloat16* pah = Ah + (size_t)gm * lda + kof + aks;
        const __nv_bfloat16* pal = Al + (size_t)gm * lda + kof + aks;
        cp16(da, pah, okA);               cp16(da + 16, pah + 8, okA);
        cp16(da + 10240, pal, okA);       cp16(da + 10240 + 16, pal + 8, okA);
        const __nv_bfloat16* pbh = Wh + (size_t)(n0 + arow) * K + ck + aks;
        const __nv_bfloat16* pbl = Wl + (size_t)(n0 + arow) * K + ck + aks;
        cp16(da + 20480, pbh, 16);        cp16(da + 20480 + 16, pbh + 8, 16);
        cp16(da + 30720, pbl, 16);        cp16(da + 30720 + 16, pbl + 8, 16);
        CP_COMMIT();
    };

    STAGE(0);

    for (int c = 0; c < NC; c++) {
        if (c + 1 < NC) {
            STAGE(c + 1);
            asm volatile("cp.async.wait_group 1;" ::: "memory");
        } else {
            asm volatile("cp.async.wait_group 0;" ::: "memory");
        }
        __syncthreads();

        const uint32_t sb = smc_u + (uint32_t)((c & 1) * STAGE_B);
#pragma unroll
        for (int ks = 0; ks < 2; ks++) {
            const uint32_t ko = (uint32_t)(ks * 32);
            uint32_t ah[2][4], bb[8][2];
            ldsm4(ah[0][0], ah[0][1], ah[0][2], ah[0][3], sb + aoff0 + ko);
            ldsm4(ah[1][0], ah[1][1], ah[1][2], ah[1][3], sb + aoff0 + 1280 + ko);
#pragma unroll
            for (int jp = 0; jp < 4; jp++)
                ldsm4(bb[2 * jp][0], bb[2 * jp][1], bb[2 * jp + 1][0], bb[2 * jp + 1][1],
                      sb + boff0 + (uint32_t)(jp * 1280) + ko);
#pragma unroll
            for (int i = 0; i < 2; i++)
#pragma unroll
                for (int j = 0; j < 8; j++) MMA_BF16(acc[i][j], ah[i], bb[j][0], bb[j][1]);

            uint32_t al[2][4];
            ldsm4(al[0][0], al[0][1], al[0][2], al[0][3], sb + 10240 + aoff0 + ko);
            ldsm4(al[1][0], al[1][1], al[1][2], al[1][3], sb + 10240 + aoff0 + 1280 + ko);
#pragma unroll
            for (int i = 0; i < 2; i++)
#pragma unroll
                for (int j = 0; j < 8; j++) MMA_BF16(acc[i][j], al[i], bb[j][0], bb[j][1]);

#pragma unroll
            for (int jp = 0; jp < 4; jp++)
                ldsm4(bb[2 * jp][0], bb[2 * jp][1], bb[2 * jp + 1][0], bb[2 * jp + 1][1],
                      sb + 10240 + boff0 + (uint32_t)(jp * 1280) + ko);
#pragma unroll
            for (int i = 0; i < 2; i++)
#pragma unroll
                for (int j = 0; j < 8; j++) MMA_BF16(acc[i][j], ah[i], bb[j][0], bb[j][1]);
        }
        __syncthreads();
    }

    // epilogue: bias + activation + hi/lo split store
#pragma unroll
    for (int i = 0; i < 2; i++) {
        int r0 = m0 + wm * 32 + i * 16 + g;
#pragma unroll
        for (int j = 0; j < 8; j++) {
            int cl = wn * 64 + j * 8 + tg * 2;
            float b0 = sbias[cl], b1 = sbias[cl + 1];
            float v0 = acc[i][j][0] + b0, v1 = acc[i][j][1] + b1;
            float v2 = acc[i][j][2] + b0, v3 = acc[i][j][3] + b1;
            if (ACT == 1) {
                v0 = fmaxf(v0, 0.f); v1 = fmaxf(v1, 0.f);
                v2 = fmaxf(v2, 0.f); v3 = fmaxf(v3, 0.f);
            }
            uint32_t hw, lw;
            if (r0 < M) {
                split_pair(v0, v1, hw, lw);
                *(uint32_t*)(Ch + (size_t)r0 * 256 + n0 + cl) = hw;
                *(uint32_t*)(Cl + (size_t)r0 * 256 + n0 + cl) = lw;
            }
            if (r0 + 8 < M) {
                split_pair(v2, v3, hw, lw);
                *(uint32_t*)(Ch + (size_t)(r0 + 8) * 256 + n0 + cl) = hw;
                *(uint32_t*)(Cl + (size_t)(r0 + 8) * 256 + n0 + cl) = lw;
            }
        }
    }
}

// ---------------- CSR build ----------------
__global__ void count_kernel(const int* __restrict__ dst, int* __restrict__ cnt) {
    int e = blockIdx.x * blockDim.x + threadIdx.x;
    if (e < NE) atomicAdd(&cnt[dst[e]], 1);
}

__global__ __launch_bounds__(1024) void scan_kernel(const int* __restrict__ cnt,
                                                    int* __restrict__ rowptr,
                                                    int* __restrict__ fill) {
    __shared__ int wsum[32];
    __shared__ int s_carry;
    const int tid = threadIdx.x, lane = tid & 31, wid = tid >> 5;
    if (tid == 0) { s_carry = 0; rowptr[0] = 0; }
    __syncthreads();
    for (int base = 0; base < NN; base += 1024) {
        int i = base + tid;
        int v = (i < NN) ? cnt[i] : 0;
        int s = v;
#pragma unroll
        for (int d = 1; d < 32; d <<= 1) {
            int y = __shfl_up_sync(0xffffffffu, s, d);
            if (lane >= d) s += y;
        }
        if (lane == 31) wsum[wid] = s;
        int carry_in = s_carry;
        __syncthreads();
        if (wid == 0) {
            int ws = wsum[lane];
#pragma unroll
            for (int d = 1; d < 32; d <<= 1) {
                int y = __shfl_up_sync(0xffffffffu, ws, d);
                if (lane >= d) ws += y;
            }
            wsum[lane] = ws;
        }
        __syncthreads();
        int off = (wid ? wsum[wid - 1] : 0) + carry_in;
        int inc = s + off;
        if (i < NN) {
            rowptr[i + 1] = inc;
            fill[i] = inc - v;
        }
        __syncthreads();
        if (tid == 1023) s_carry = inc;
        __syncthreads();
    }
}

__global__ void scatter_kernel(const int* __restrict__ src, const int* __restrict__ dst,
                               int* __restrict__ fill, int* __restrict__ col) {
    int e = blockIdx.x * blockDim.x + threadIdx.x;
    if (e < NE) {
        int slot = atomicAdd(&fill[dst[e]], 1);
        col[slot] = src[e];
    }
}

// ---------------- atomic-free aggregation (4 nodes/block, 1 warp each) --------------
__device__ __forceinline__ void acc8(float* acc, uint4 hv, uint4 lv) {
    const uint32_t* h = (const uint32_t*)&hv;
    const uint32_t* l = (const uint32_t*)&lv;
#pragma unroll
    for (int p = 0; p < 4; p++) {
        __nv_bfloat162 h2 = *reinterpret_cast<const __nv_bfloat162*>(&h[p]);
        __nv_bfloat162 l2 = *reinterpret_cast<const __nv_bfloat162*>(&l[p]);
        acc[2 * p]     += __low2float(h2)  + __low2float(l2);
        acc[2 * p + 1] += __high2float(h2) + __high2float(l2);
    }
}

__global__ __launch_bounds__(128) void agg_kernel(
    const __nv_bfloat16* __restrict__ th, const __nv_bfloat16* __restrict__ tl,
    const int* __restrict__ rowptr, const int* __restrict__ col,
    __nv_bfloat16* __restrict__ aggh, __nv_bfloat16* __restrict__ aggl)
{
    const int node = blockIdx.x * 4 + (threadIdx.x >> 5);
    if (node >= NN) return;
    const int tid = threadIdx.x & 31;
    const int s = rowptr[node];
    const int e = rowptr[node + 1];
    float acc[8];
#pragma unroll
    for (int p = 0; p < 8; p++) acc[p] = 0.f;

    int i = s;
    for (; i + 4 <= e; i += 4) {
        int c0 = __ldg(&col[i]),     c1 = __ldg(&col[i + 1]);
        int c2 = __ldg(&col[i + 2]), c3 = __ldg(&col[i + 3]);
        uint4 h0 = *(const uint4*)(th + (size_t)c0 * HID + tid * 8);
        uint4 l0 = *(const uint4*)(tl + (size_t)c0 * HID + tid * 8);
        uint4 h1 = *(const uint4*)(th + (size_t)c1 * HID + tid * 8);
        uint4 l1 = *(const uint4*)(tl + (size_t)c1 * HID + tid * 8);
        uint4 h2 = *(const uint4*)(th + (size_t)c2 * HID + tid * 8);
        uint4 l2 = *(const uint4*)(tl + (size_t)c2 * HID + tid * 8);
        uint4 h3 = *(const uint4*)(th + (size_t)c3 * HID + tid * 8);
        uint4 l3 = *(const uint4*)(tl + (size_t)c3 * HID + tid * 8);
        acc8(acc, h0, l0); acc8(acc, h1, l1);
        acc8(acc, h2, l2); acc8(acc, h3, l3);
    }
    for (; i < e; i++) {
        int c0 = __ldg(&col[i]);
        uint4 h0 = *(const uint4*)(th + (size_t)c0 * HID + tid * 8);
        uint4 l0 = *(const uint4*)(tl + (size_t)c0 * HID + tid * 8);
        acc8(acc, h0, l0);
    }

    uint32_t hw[4], lw[4];
#pragma unroll
    for (int p = 0; p < 4; p++) split_pair(acc[2 * p], acc[2 * p + 1], hw[p], lw[p]);
    *(uint4*)(aggh + (size_t)node * HID + tid * 8) = *(uint4*)hw;
    *(uint4*)(aggl + (size_t)node * HID + tid * 8) = *(uint4*)lw;
}

// ---------------- output projection: out = tanh(u @ W2 + b2) ----------------
__global__ __launch_bounds__(256) void out_kernel(
    const __nv_bfloat16* __restrict__ uh, const __nv_bfloat16* __restrict__ ul,
    const float* __restrict__ w, const float* __restrict__ b,
    float* __restrict__ out, int M)
{
    __shared__ float ws[256 * 16];
    __shared__ float bs[16];
    const int tid = threadIdx.x;
    for (int i = tid; i < 256 * 16 / 4; i += 256)
        ((float4*)ws)[i] = ((const float4*)w)[i];
    if (tid < 16) bs[tid] = b[tid];
    __syncthreads();

    const int mloc = tid >> 1;
    const int off  = (tid & 1) * 8;
    const int m = blockIdx.x * 128 + mloc;
    if (m >= M) return;

    float acc[8];
#pragma unroll
    for (int j = 0; j < 8; j++) acc[j] = bs[off + j];

    const uint4* ph = (const uint4*)(uh + (size_t)m * HID);
    const uint4* pl = (const uint4*)(ul + (size_t)m * HID);
#pragma unroll 4
    for (int kc = 0; kc < 32; kc++) {
        uint4 hv = ph[kc], lv = pl[kc];
        const uint32_t* hp = (const uint32_t*)&hv;
        const uint32_t* lp = (const uint32_t*)&lv;
        float f[8];
#pragma unroll
        for (int p = 0; p < 4; p++) {
            __nv_bfloat162 h2 = *reinterpret_cast<const __nv_bfloat162*>(&hp[p]);
            __nv_bfloat162 l2 = *reinterpret_cast<const __nv_bfloat162*>(&lp[p]);
            f[2 * p]     = __low2float(h2)  + __low2float(l2);
            f[2 * p + 1] = __high2float(h2) + __high2float(l2);
        }
#pragma unroll
        for (int qv = 0; qv < 8; qv++) {
            const float* wr = &ws[(kc * 8 + qv) * 16 + off];
#pragma unroll
            for (int j = 0; j < 8; j++) acc[j] += f[qv] * wr[j];
        }
    }
    float o[8];
#pragma unroll
    for (int j = 0; j < 8; j++) o[j] = tanhf(acc[j]);
    float* op = out + (size_t)m * 16 + off;
    *(float4*)(op)     = *(float4*)&o[0];
    *(float4*)(op + 4) = *(float4*)&o[4];
}

// ---------------- launcher ----------------
extern "C" void kernel_launch(void* const* d_in, const int* in_sizes, int n_in,
                              void* d_out, int out_size) {
    const float* x       = (const float*)d_in[0];
    const int*   ei      = (const int*)d_in[1];
    const float* pre_w1  = (const float*)d_in[2];
    const float* pre_b1  = (const float*)d_in[3];
    const float* pre_w2  = (const float*)d_in[4];
    const float* pre_b2  = (const float*)d_in[5];
    const float* conv_w  = (const float*)d_in[6];
    const float* conv_b  = (const float*)d_in[7];
    const float* post_w1 = (const float*)d_in[8];
    const float* post_b1 = (const float*)d_in[9];
    const float* post_w2 = (const float*)d_in[10];
    const float* post_b2 = (const float*)d_in[11];
    float* out = (float*)d_out;

    const int* src = ei;
    const int* dst = ei + NE;

    __nv_bfloat16 *ah, *al, *th, *tl, *gh, *gl, *uh, *ul;
    int *cnt, *rowptr, *fill, *col;
    float *bpart, *cbt, *cbu;
    __nv_bfloat16 *wth, *wtl, *wuh, *wul;
    cudaGetSymbolAddress((void**)&ah, g_ah);   cudaGetSymbolAddress((void**)&al, g_al);
    cudaGetSymbolAddress((void**)&th, g_th);   cudaGetSymbolAddress((void**)&tl, g_tl);
    cudaGetSymbolAddress((void**)&gh, g_gh);   cudaGetSymbolAddress((void**)&gl, g_gl);
    cudaGetSymbolAddress((void**)&uh, g_uh);   cudaGetSymbolAddress((void**)&ul, g_ul);
    cudaGetSymbolAddress((void**)&cnt, g_cnt);
    cudaGetSymbolAddress((void**)&rowptr, g_rowptr);
    cudaGetSymbolAddress((void**)&fill, g_fill);
    cudaGetSymbolAddress((void**)&col, g_col);
    cudaGetSymbolAddress((void**)&bpart, g_bpart);
    cudaGetSymbolAddress((void**)&cbt, g_cbt); cudaGetSymbolAddress((void**)&cbu, g_cbu);
    cudaGetSymbolAddress((void**)&wth, g_wth); cudaGetSymbolAddress((void**)&wtl, g_wtl);
    cudaGetSymbolAddress((void**)&wuh, g_wuh); cudaGetSymbolAddress((void**)&wul, g_wul);

    const float* P1 = post_w1;                 // rows 0..255 of [512][256]
    const float* P2 = post_w1 + 256 * 256;     // rows 256..511

    const int DSMEM = 2 * STAGE_B;  // 80 KB
    cudaFuncSetAttribute(mma_gemm<1>, cudaFuncAttributeMaxDynamicSharedMemorySize, DSMEM);

    cudaMemsetAsync(cnt, 0, NN * sizeof(int), 0);

    // ---- weight composition + transpose + split (h folded away) ----
    compose_prep<<<dim3(4, 4), 256>>>(pre_w2, conv_w, wth, wtl, 256, 0);   // Wt = W2@Wc
    compose_prep<<<dim3(4, 4), 256>>>(pre_w2, P1,     wuh, wul, 512, 0);   // Wp = W2@P1
    prep2<<<dim3(8, 8), dim3(32, 8)>>>(P2, wuh, wul, 512, 256);            // agg-part
    bias_part<<<dim3(8, 2), 256>>>(pre_b2, conv_w, P1, bpart);
    bias_fin<<<dim3(1, 2), 256>>>(bpart, conv_b, post_b1, cbt, cbu);

    // ---- pre-MLP layer 1 -> a pair ----
    pre_kernel<<<(NN + 31) / 32, 256>>>(x, pre_w1, pre_b1, ah, al);

    const int MT = (NN + 127) / 128;  // 391
    dim3 gg(2, MT);

    // ---- t = relu(a@Wt + bt) ----
    mma_gemm<1><<<gg, 256, DSMEM>>>(ah, al, nullptr, nullptr, wth, wtl, cbt,
                                    th, tl, NN, 256, 256);

    // ---- CSR build + atomic-free segment sum ----
    count_kernel<<<(NE + 255) / 256, 256>>>(dst, cnt);
    scan_kernel<<<1, 1024>>>(cnt, rowptr, fill);
    scatter_kernel<<<(NE + 255) / 256, 256>>>(src, dst, fill, col);
    agg_kernel<<<(NN + 3) / 4, 128>>>(th, tl, rowptr, col, gh, gl);

    // ---- u = relu(a@Wp + agg@P2 + bu)  (K=512 concat) ----
    mma_gemm<1><<<gg, 256, DSMEM>>>(ah, al, gh, gl, wuh, wul, cbu,
                                    uh, ul, NN, 512, 256);
    // ---- out = tanh(u@post_w2 + post_b2) ----
    out_kernel<<<(NN + 127) / 128, 256>>>(uh, ul, post_w2, post_b2, out, NN);
}

// round 7
// speedup vs baseline: 1.8881x; 1.0081x over previous
#include <cuda_runtime.h>
#include <cuda_bf16.h>
#include <cstdint>
#include <cstddef>

#define NN 50000
#define NE 800000
#define HID 256

// smem stage layout (bytes, pitch 80/row of 32 bf16 + pad):
// Ah[128x80]=10240 | Al=10240 | Bh[128x80]=10240 | Bl=10240
#define STAGE_B 40960

// ---------------- scratch (device globals: no allocation allowed) ----------------
__device__ __nv_bfloat16 g_ah[(size_t)NN * HID], g_al[(size_t)NN * HID];
__device__ __nv_bfloat16 g_th[(size_t)NN * HID], g_tl[(size_t)NN * HID];
__device__ __nv_bfloat16 g_gh[(size_t)NN * HID], g_gl[(size_t)NN * HID];
__device__ __nv_bfloat16 g_uh[(size_t)NN * HID], g_ul[(size_t)NN * HID];
__device__ int g_cnt[NN];
__device__ int g_rowptr[NN + 1];
__device__ int g_fill[NN];
__device__ int g_col[NE];
// composed biases
__device__ float g_cbt[256];         // b2@Wc + conv_b
__device__ float g_cbu[256];         // b2@P1 + post_b1
// split/transposed weights: [N=256][K] bf16, hi+lo
__device__ __nv_bfloat16 g_wth[256 * 256], g_wtl[256 * 256];   // t-GEMM weights
__device__ __nv_bfloat16 g_wuh[256 * 512], g_wul[256 * 512];   // u-GEMM weights (stacked)

// ---------------- helpers ----------------
__device__ __forceinline__ uint32_t s2u(const void* p) {
    uint32_t a;
    asm("{ .reg .u64 t; cvta.to.shared.u64 t, %1; cvt.u32.u64 %0, t; }" : "=r"(a) : "l"(p));
    return a;
}
__device__ __forceinline__ void cp16(uint32_t dst, const void* src, int srcsz) {
    asm volatile("cp.async.cg.shared.global [%0], [%1], 16, %2;"
                 :: "r"(dst), "l"(src), "r"(srcsz) : "memory");
}
#define CP_COMMIT() asm volatile("cp.async.commit_group;" ::: "memory")

__device__ __forceinline__ void ldsm4(uint32_t& r0, uint32_t& r1, uint32_t& r2, uint32_t& r3,
                                      uint32_t addr) {
    asm volatile("ldmatrix.sync.aligned.m8n8.x4.shared.b16 {%0,%1,%2,%3}, [%4];"
                 : "=r"(r0), "=r"(r1), "=r"(r2), "=r"(r3) : "r"(addr));
}

#define MMA_BF16(cc, aa, b0v, b1v)                                              \
    asm volatile(                                                               \
        "mma.sync.aligned.m16n8k16.row.col.f32.bf16.bf16.f32 "                  \
        "{%0,%1,%2,%3}, {%4,%5,%6,%7}, {%8,%9}, {%0,%1,%2,%3};"                 \
        : "+f"(cc[0]), "+f"(cc[1]), "+f"(cc[2]), "+f"(cc[3])                    \
        : "r"(aa[0]), "r"(aa[1]), "r"(aa[2]), "r"(aa[3]), "r"(b0v), "r"(b1v))

__device__ __forceinline__ uint32_t pack_bf16x2(float a, float b) {
    __nv_bfloat162 p = __float22bfloat162_rn(make_float2(a, b));
    return *reinterpret_cast<uint32_t*>(&p);
}
__device__ __forceinline__ void split_pair(float v0, float v1, uint32_t& hw, uint32_t& lw) {
    float h0 = __bfloat162float(__float2bfloat16_rn(v0));
    float h1 = __bfloat162float(__float2bfloat16_rn(v1));
    hw = pack_bf16x2(h0, h1);
    lw = pack_bf16x2(v0 - h0, v1 - h1);
}

// ---------------- fused compose+prep+bias ----------------
// by<4: hi/lo[n][koff+k] = split((A@B)[k][n]).   by==4: bout = b2@B + badd.
__global__ __launch_bounds__(256) void compose_prep(
    const float* __restrict__ A, const float* __restrict__ B,
    __nv_bfloat16* __restrict__ hi, __nv_bfloat16* __restrict__ lo,
    int kpitch, int koff,
    const float* __restrict__ b2, const float* __restrict__ badd,
    float* __restrict__ bout)
{
    const int t = threadIdx.x;
    if (blockIdx.y == 4) {
        // bias composition: 4 blocks x 64 cols, 4-way k-split
        __shared__ float red[4][64];
        int j = blockIdx.x * 64 + (t & 63);
        int ks = t >> 6;
        float acc = 0.f;
#pragma unroll 8
        for (int k = ks * 64; k < ks * 64 + 64; k++)
            acc += b2[k] * B[(size_t)k * 256 + j];
        red[ks][t & 63] = acc;
        __syncthreads();
        if (t < 64) {
            int jj = blockIdx.x * 64 + t;
            bout[jj] = red[0][t] + red[1][t] + red[2][t] + red[3][t] + badd[jj];
        }
        return;
    }

    __shared__ float As[16][64];
    __shared__ float Bs[16][64];
    const int tx = t & 15, ty = t >> 4;
    const int m0 = blockIdx.y * 64, n0 = blockIdx.x * 64;
    float acc[4][4];
#pragma unroll
    for (int i = 0; i < 4; i++)
#pragma unroll
        for (int j = 0; j < 4; j++) acc[i][j] = 0.f;

    for (int k0 = 0; k0 < 256; k0 += 16) {
#pragma unroll
        for (int i = 0; i < 4; i++) {
            int idx = t + i * 256;
            int r = idx >> 4, c = idx & 15;
            As[c][r] = A[(size_t)(m0 + r) * 256 + k0 + c];
        }
#pragma unroll
        for (int i = 0; i < 4; i++) {
            int idx = t + i * 256;
            int r = idx >> 6, c = idx & 63;
            Bs[r][c] = B[(size_t)(k0 + r) * 256 + n0 + c];
        }
        __syncthreads();
#pragma unroll
        for (int k = 0; k < 16; k++) {
            float ra[4], rb[4];
#pragma unroll
            for (int i = 0; i < 4; i++) ra[i] = As[k][ty * 4 + i];
#pragma unroll
            for (int j = 0; j < 4; j++) rb[j] = Bs[k][tx * 4 + j];
#pragma unroll
            for (int i = 0; i < 4; i++)
#pragma unroll
                for (int j = 0; j < 4; j++) acc[i][j] += ra[i] * rb[j];
        }
        __syncthreads();
    }
#pragma unroll
    for (int i = 0; i < 4; i++) {
        int kk = m0 + ty * 4 + i;
#pragma unroll
        for (int j = 0; j < 4; j++) {
            int nn = n0 + tx * 4 + j;
            float v = acc[i][j];
            __nv_bfloat16 h = __float2bfloat16_rn(v);
            hi[(size_t)nn * kpitch + koff + kk] = h;
            lo[(size_t)nn * kpitch + koff + kk] =
                __float2bfloat16_rn(v - __bfloat162float(h));
        }
    }
}

// ---------------- prep (transpose + split only, for P2) ----------------
__global__ void prep2(const float* __restrict__ W, __nv_bfloat16* __restrict__ hi,
                      __nv_bfloat16* __restrict__ lo, int kpitch, int koff) {
    __shared__ float tile[32][33];
    int k0 = blockIdx.y * 32, n0 = blockIdx.x * 32;
    int tx = threadIdx.x, ty = threadIdx.y;  // 32 x 8
    for (int i = ty; i < 32; i += 8) tile[i][tx] = W[(size_t)(k0 + i) * 256 + n0 + tx];
    __syncthreads();
    for (int i = ty; i < 32; i += 8) {
        float v = tile[tx][i];  // = W[k0+tx][n0+i]
        __nv_bfloat16 h = __float2bfloat16_rn(v);
        hi[(size_t)(n0 + i) * kpitch + koff + k0 + tx] = h;
        lo[(size_t)(n0 + i) * kpitch + koff + k0 + tx] =
            __float2bfloat16_rn(v - __bfloat162float(h));
    }
}

// ---------------- pre-MLP layer 1: a = relu(x@w1+b1), K=16, hi/lo out ---------------
__global__ __launch_bounds__(256) void pre_kernel(
    const float* __restrict__ x, const float* __restrict__ w1, const float* __restrict__ b1,
    __nv_bfloat16* __restrict__ Ch, __nv_bfloat16* __restrict__ Cl)
{
    __shared__ float ws[16 * 256];
    __shared__ float bs[256];
    const int tid = threadIdx.x;
    for (int i = tid; i < 1024; i += 256) ((float4*)ws)[i] = ((const float4*)w1)[i];
    bs[tid] = b1[tid];
    __syncthreads();

    const int warp = tid >> 5, lane = tid & 31;
#pragma unroll
    for (int r = 0; r < 4; r++) {
        int row = blockIdx.x * 32 + warp * 4 + r;
        if (row >= NN) break;
        float xv[16];
        const float4* xp = (const float4*)(x + (size_t)row * 16);
#pragma unroll
        for (int q = 0; q < 4; q++) *(float4*)&xv[q * 4] = xp[q];
        float acc[8];
#pragma unroll
        for (int j = 0; j < 8; j++) acc[j] = bs[lane + 32 * j];
#pragma unroll
        for (int k = 0; k < 16; k++) {
            float xk = xv[k];
            const float* wr = &ws[k * 256 + lane];
#pragma unroll
            for (int j = 0; j < 8; j++) acc[j] += xk * wr[32 * j];
        }
#pragma unroll
        for (int j = 0; j < 8; j++) {
            float v = fmaxf(acc[j], 0.f);
            __nv_bfloat16 h = __float2bfloat16_rn(v);
            Ch[(size_t)row * 256 + lane + 32 * j] = h;
            Cl[(size_t)row * 256 + lane + 32 * j] =
                __float2bfloat16_rn(v - __bfloat162float(h));
        }
    }
}

// ---------------- tensor-core GEMM: C(hi/lo) = act(concat(A1,A2) @ W + bias) ----------
template <int ACT>
__global__ __launch_bounds__(256, 2) void mma_gemm(
    const __nv_bfloat16* __restrict__ A1h, const __nv_bfloat16* __restrict__ A1l,
    const __nv_bfloat16* __restrict__ A2h, const __nv_bfloat16* __restrict__ A2l,
    const __nv_bfloat16* __restrict__ Wh,  const __nv_bfloat16* __restrict__ Wl,
    const float* __restrict__ bias,
    __nv_bfloat16* __restrict__ Ch, __nv_bfloat16* __restrict__ Cl,
    int M, int K, int K1)
{
    extern __shared__ char smc[];
    __shared__ float sbias[128];

    const int tid = threadIdx.x;
    const int wid = tid >> 5, lane = tid & 31;
    const int g = lane >> 2, tg = lane & 3;
    const int wm = wid >> 1, wn = wid & 1;
    const int m0 = blockIdx.y * 128, n0 = blockIdx.x * 128;
    const uint32_t smc_u = s2u(smc);

    if (tid < 128) sbias[tid] = bias[n0 + tid];

    const int arow = tid >> 1;
    const int aks  = (tid & 1) * 16;
    const int gm   = m0 + arow;
    const int okA  = (gm < M) ? 16 : 0;

    const int q = lane >> 3, rr = lane & 7;
    const uint32_t aoff0 = (uint32_t)((wm * 32 + (q & 1) * 8 + rr) * 80 + (q >> 1) * 16);
    const uint32_t boff0 = (uint32_t)(20480 + (wn * 64 + (q >> 1) * 8 + rr) * 80 + (q & 1) * 16);

    float acc[2][8][4];
#pragma unroll
    for (int i = 0; i < 2; i++)
#pragma unroll
        for (int j = 0; j < 8; j++)
#pragma unroll
            for (int p = 0; p < 4; p++) acc[i][j][p] = 0.f;

    const int NC = K >> 5;

    auto STAGE = [&](int c) {
        const int ck = c * 32;
        const __nv_bfloat16 *Ah, *Al; int lda, kof;
        if (ck < K1) { Ah = A1h; Al = A1l; lda = K1;     kof = ck; }
        else         { Ah = A2h; Al = A2l; lda = K - K1; kof = ck - K1; }
        const uint32_t sb = smc_u + (uint32_t)((c & 1) * STAGE_B);
        const uint32_t da = sb + (uint32_t)(arow * 80 + (tid & 1) * 32);
        const __nv_bfloat16* pah = Ah + (size_t)gm * lda + kof + aks;
        const __nv_bfloat16* pal = Al + (size_t)gm * lda + kof + aks;
        cp16(da, pah, okA);               cp16(da + 16, pah + 8, okA);
        cp16(da + 10240, pal, okA);       cp16(da + 10240 + 16, pal + 8, okA);
        const __nv_bfloat16* pbh = Wh + (size_t)(n0 + arow) * K + ck + aks;
        const __nv_bfloat16* pbl = Wl + (size_t)(n0 + arow) * K + ck + aks;
        cp16(da + 20480, pbh, 16);        cp16(da + 20480 + 16, pbh + 8, 16);
        cp16(da + 30720, pbl, 16);        cp16(da + 30720 + 16, pbl + 8, 16);
        CP_COMMIT();
    };

    STAGE(0);

    for (int c = 0; c < NC; c++) {
        if (c + 1 < NC) {
            STAGE(c + 1);
            asm volatile("cp.async.wait_group 1;" ::: "memory");
        } else {
            asm volatile("cp.async.wait_group 0;" ::: "memory");
        }
        __syncthreads();

        const uint32_t sb = smc_u + (uint32_t)((c & 1) * STAGE_B);
#pragma unroll
        for (int ks = 0; ks < 2; ks++) {
            const uint32_t ko = (uint32_t)(ks * 32);
            uint32_t ah[2][4], bb[8][2];
            ldsm4(ah[0][0], ah[0][1], ah[0][2], ah[0][3], sb + aoff0 + ko);
            ldsm4(ah[1][0], ah[1][1], ah[1][2], ah[1][3], sb + aoff0 + 1280 + ko);
#pragma unroll
            for (int jp = 0; jp < 4; jp++)
                ldsm4(bb[2 * jp][0], bb[2 * jp][1], bb[2 * jp + 1][0], bb[2 * jp + 1][1],
                      sb + boff0 + (uint32_t)(jp * 1280) + ko);
#pragma unroll
            for (int i = 0; i < 2; i++)
#pragma unroll
                for (int j = 0; j < 8; j++) MMA_BF16(acc[i][j], ah[i], bb[j][0], bb[j][1]);

            uint32_t al[2][4];
            ldsm4(al[0][0], al[0][1], al[0][2], al[0][3], sb + 10240 + aoff0 + ko);
            ldsm4(al[1][0], al[1][1], al[1][2], al[1][3], sb + 10240 + aoff0 + 1280 + ko);
#pragma unroll
            for (int i = 0; i < 2; i++)
#pragma unroll
                for (int j = 0; j < 8; j++) MMA_BF16(acc[i][j], al[i], bb[j][0], bb[j][1]);

#pragma unroll
            for (int jp = 0; jp < 4; jp++)
                ldsm4(bb[2 * jp][0], bb[2 * jp][1], bb[2 * jp + 1][0], bb[2 * jp + 1][1],
                      sb + 10240 + boff0 + (uint32_t)(jp * 1280) + ko);
#pragma unroll
            for (int i = 0; i < 2; i++)
#pragma unroll
                for (int j = 0; j < 8; j++) MMA_BF16(acc[i][j], ah[i], bb[j][0], bb[j][1]);
        }
        __syncthreads();
    }

    // epilogue: bias + activation + hi/lo split store
#pragma unroll
    for (int i = 0; i < 2; i++) {
        int r0 = m0 + wm * 32 + i * 16 + g;
#pragma unroll
        for (int j = 0; j < 8; j++) {
            int cl = wn * 64 + j * 8 + tg * 2;
            float b0 = sbias[cl], b1 = sbias[cl + 1];
            float v0 = acc[i][j][0] + b0, v1 = acc[i][j][1] + b1;
            float v2 = acc[i][j][2] + b0, v3 = acc[i][j][3] + b1;
            if (ACT == 1) {
                v0 = fmaxf(v0, 0.f); v1 = fmaxf(v1, 0.f);
                v2 = fmaxf(v2, 0.f); v3 = fmaxf(v3, 0.f);
            }
            uint32_t hw, lw;
            if (r0 < M) {
                split_pair(v0, v1, hw, lw);
                *(uint32_t*)(Ch + (size_t)r0 * 256 + n0 + cl) = hw;
                *(uint32_t*)(Cl + (size_t)r0 * 256 + n0 + cl) = lw;
            }
            if (r0 + 8 < M) {
                split_pair(v2, v3, hw, lw);
                *(uint32_t*)(Ch + (size_t)(r0 + 8) * 256 + n0 + cl) = hw;
                *(uint32_t*)(Cl + (size_t)(r0 + 8) * 256 + n0 + cl) = lw;
            }
        }
    }
}

// ---------------- CSR build ----------------
__global__ void count_kernel(const int* __restrict__ dst, int* __restrict__ cnt) {
    int e = blockIdx.x * blockDim.x + threadIdx.x;
    if (e < NE) atomicAdd(&cnt[dst[e]], 1);
}

__global__ __launch_bounds__(1024) void scan_kernel(const int* __restrict__ cnt,
                                                    int* __restrict__ rowptr,
                                                    int* __restrict__ fill) {
    __shared__ int wsum[32];
    __shared__ int s_carry;
    const int tid = threadIdx.x, lane = tid & 31, wid = tid >> 5;
    if (tid == 0) { s_carry = 0; rowptr[0] = 0; }
    __syncthreads();
    for (int base = 0; base < NN; base += 1024) {
        int i = base + tid;
        int v = (i < NN) ? cnt[i] : 0;
        int s = v;
#pragma unroll
        for (int d = 1; d < 32; d <<= 1) {
            int y = __shfl_up_sync(0xffffffffu, s, d);
            if (lane >= d) s += y;
        }
        if (lane == 31) wsum[wid] = s;
        int carry_in = s_carry;
        __syncthreads();
        if (wid == 0) {
            int ws = wsum[lane];
#pragma unroll
            for (int d = 1; d < 32; d <<= 1) {
                int y = __shfl_up_sync(0xffffffffu, ws, d);
                if (lane >= d) ws += y;
            }
            wsum[lane] = ws;
        }
        __syncthreads();
        int off = (wid ? wsum[wid - 1] : 0) + carry_in;
        int inc = s + off;
        if (i < NN) {
            rowptr[i + 1] = inc;
            fill[i] = inc - v;
        }
        __syncthreads();
        if (tid == 1023) s_carry = inc;
        __syncthreads();
    }
}

__global__ void scatter_kernel(const int* __restrict__ src, const int* __restrict__ dst,
                               int* __restrict__ fill, int* __restrict__ col) {
    int e = blockIdx.x * blockDim.x + threadIdx.x;
    if (e < NE) {
        int slot = atomicAdd(&fill[dst[e]], 1);
        col[slot] = src[e];
    }
}

// ---------------- atomic-free aggregation (4 nodes/block, 1 warp each) --------------
__device__ __forceinline__ void acc8(float* acc, uint4 hv, uint4 lv) {
    const uint32_t* h = (const uint32_t*)&hv;
    const uint32_t* l = (const uint32_t*)&lv;
#pragma unroll
    for (int p = 0; p < 4; p++) {
        __nv_bfloat162 h2 = *reinterpret_cast<const __nv_bfloat162*>(&h[p]);
        __nv_bfloat162 l2 = *reinterpret_cast<const __nv_bfloat162*>(&l[p]);
        acc[2 * p]     += __low2float(h2)  + __low2float(l2);
        acc[2 * p + 1] += __high2float(h2) + __high2float(l2);
    }
}

__global__ __launch_bounds__(128) void agg_kernel(
    const __nv_bfloat16* __restrict__ th, const __nv_bfloat16* __restrict__ tl,
    const int* __restrict__ rowptr, const int* __restrict__ col,
    __nv_bfloat16* __restrict__ aggh, __nv_bfloat16* __restrict__ aggl)
{
    const int node = blockIdx.x * 4 + (threadIdx.x >> 5);
    if (node >= NN) return;
    const int tid = threadIdx.x & 31;
    const int s = rowptr[node];
    const int e = rowptr[node + 1];
    float acc[8];
#pragma unroll
    for (int p = 0; p < 8; p++) acc[p] = 0.f;

    int i = s;
    for (; i + 4 <= e; i += 4) {
        int c0 = __ldg(&col[i]),     c1 = __ldg(&col[i + 1]);
        int c2 = __ldg(&col[i + 2]), c3 = __ldg(&col[i + 3]);
        uint4 h0 = *(const uint4*)(th + (size_t)c0 * HID + tid * 8);
        uint4 l0 = *(const uint4*)(tl + (size_t)c0 * HID + tid * 8);
        uint4 h1 = *(const uint4*)(th + (size_t)c1 * HID + tid * 8);
        uint4 l1 = *(const uint4*)(tl + (size_t)c1 * HID + tid * 8);
        uint4 h2 = *(const uint4*)(th + (size_t)c2 * HID + tid * 8);
        uint4 l2 = *(const uint4*)(tl + (size_t)c2 * HID + tid * 8);
        uint4 h3 = *(const uint4*)(th + (size_t)c3 * HID + tid * 8);
        uint4 l3 = *(const uint4*)(tl + (size_t)c3 * HID + tid * 8);
        acc8(acc, h0, l0); acc8(acc, h1, l1);
        acc8(acc, h2, l2); acc8(acc, h3, l3);
    }
    for (; i < e; i++) {
        int c0 = __ldg(&col[i]);
        uint4 h0 = *(const uint4*)(th + (size_t)c0 * HID + tid * 8);
        uint4 l0 = *(const uint4*)(tl + (size_t)c0 * HID + tid * 8);
        acc8(acc, h0, l0);
    }

    uint32_t hw[4], lw[4];
#pragma unroll
    for (int p = 0; p < 4; p++) split_pair(acc[2 * p], acc[2 * p + 1], hw[p], lw[p]);
    *(uint4*)(aggh + (size_t)node * HID + tid * 8) = *(uint4*)hw;
    *(uint4*)(aggl + (size_t)node * HID + tid * 8) = *(uint4*)lw;
}

// ---------------- output projection: out = tanh(u @ W2 + b2) ----------------
__global__ __launch_bounds__(256) void out_kernel(
    const __nv_bfloat16* __restrict__ uh, const __nv_bfloat16* __restrict__ ul,
    const float* __restrict__ w, const float* __restrict__ b,
    float* __restrict__ out, int M)
{
    __shared__ float ws[256 * 16];
    __shared__ float bs[16];
    const int tid = threadIdx.x;
    for (int i = tid; i < 256 * 16 / 4; i += 256)
        ((float4*)ws)[i] = ((const float4*)w)[i];
    if (tid < 16) bs[tid] = b[tid];
    __syncthreads();

    const int mloc = tid >> 1;
    const int off  = (tid & 1) * 8;
    const int m = blockIdx.x * 128 + mloc;
    if (m >= M) return;

    float acc[8];
#pragma unroll
    for (int j = 0; j < 8; j++) acc[j] = bs[off + j];

    const uint4* ph = (const uint4*)(uh + (size_t)m * HID);
    const uint4* pl = (const uint4*)(ul + (size_t)m * HID);
#pragma unroll 4
    for (int kc = 0; kc < 32; kc++) {
        uint4 hv = ph[kc], lv = pl[kc];
        const uint32_t* hp = (const uint32_t*)&hv;
        const uint32_t* lp = (const uint32_t*)&lv;
        float f[8];
#pragma unroll
        for (int p = 0; p < 4; p++) {
            __nv_bfloat162 h2 = *reinterpret_cast<const __nv_bfloat162*>(&hp[p]);
            __nv_bfloat162 l2 = *reinterpret_cast<const __nv_bfloat162*>(&lp[p]);
            f[2 * p]     = __low2float(h2)  + __low2float(l2);
            f[2 * p + 1] = __high2float(h2) + __high2float(l2);
        }
#pragma unroll
        for (int qv = 0; qv < 8; qv++) {
            const float* wr = &ws[(kc * 8 + qv) * 16 + off];
#pragma unroll
            for (int j = 0; j < 8; j++) acc[j] += f[qv] * wr[j];
        }
    }
    float o[8];
#pragma unroll
    for (int j = 0; j < 8; j++) o[j] = tanhf(acc[j]);
    float* op = out + (size_t)m * 16 + off;
    *(float4*)(op)     = *(float4*)&o[0];
    *(float4*)(op + 4) = *(float4*)&o[4];
}

// ---------------- launcher ----------------
extern "C" void kernel_launch(void* const* d_in, const int* in_sizes, int n_in,
                              void* d_out, int out_size) {
    const float* x       = (const float*)d_in[0];
    const int*   ei      = (const int*)d_in[1];
    const float* pre_w1  = (const float*)d_in[2];
    const float* pre_b1  = (const float*)d_in[3];
    const float* pre_w2  = (const float*)d_in[4];
    const float* pre_b2  = (const float*)d_in[5];
    const float* conv_w  = (const float*)d_in[6];
    const float* conv_b  = (const float*)d_in[7];
    const float* post_w1 = (const float*)d_in[8];
    const float* post_b1 = (const float*)d_in[9];
    const float* post_w2 = (const float*)d_in[10];
    const float* post_b2 = (const float*)d_in[11];
    float* out = (float*)d_out;

    const int* src = ei;
    const int* dst = ei + NE;

    __nv_bfloat16 *ah, *al, *th, *tl, *gh, *gl, *uh, *ul;
    int *cnt, *rowptr, *fill, *col;
    float *cbt, *cbu;
    __nv_bfloat16 *wth, *wtl, *wuh, *wul;
    cudaGetSymbolAddress((void**)&ah, g_ah);   cudaGetSymbolAddress((void**)&al, g_al);
    cudaGetSymbolAddress((void**)&th, g_th);   cudaGetSymbolAddress((void**)&tl, g_tl);
    cudaGetSymbolAddress((void**)&gh, g_gh);   cudaGetSymbolAddress((void**)&gl, g_gl);
    cudaGetSymbolAddress((void**)&uh, g_uh);   cudaGetSymbolAddress((void**)&ul, g_ul);
    cudaGetSymbolAddress((void**)&cnt, g_cnt);
    cudaGetSymbolAddress((void**)&rowptr, g_rowptr);
    cudaGetSymbolAddress((void**)&fill, g_fill);
    cudaGetSymbolAddress((void**)&col, g_col);
    cudaGetSymbolAddress((void**)&cbt, g_cbt); cudaGetSymbolAddress((void**)&cbu, g_cbu);
    cudaGetSymbolAddress((void**)&wth, g_wth); cudaGetSymbolAddress((void**)&wtl, g_wtl);
    cudaGetSymbolAddress((void**)&wuh, g_wuh); cudaGetSymbolAddress((void**)&wul, g_wul);

    const float* P1 = post_w1;                 // rows 0..255 of [512][256]
    const float* P2 = post_w1 + 256 * 256;     // rows 256..511

    const int DSMEM = 2 * STAGE_B;  // 80 KB
    cudaFuncSetAttribute(mma_gemm<1>, cudaFuncAttributeMaxDynamicSharedMemorySize, DSMEM);

    const int MT = (NN + 127) / 128;  // 391
    dim3 gg(2, MT);

    // (1) t-weights + t-bias:  Wt = W2@Wc (transposed/split), bt = b2@Wc + conv_b
    compose_prep<<<dim3(4, 5), 256>>>(pre_w2, conv_w, wth, wtl, 256, 0,
                                      pre_b2, conv_b, cbt);
    // (2) pre-MLP layer 1 -> a pair
    pre_kernel<<<(NN + 31) / 32, 256>>>(x, pre_w1, pre_b1, ah, al);
    // (3) u-weights a-part + u-bias:  Wp = W2@P1, bu = b2@P1 + post_b1
    compose_prep<<<dim3(4, 5), 256>>>(pre_w2, P1, wuh, wul, 512, 0,
                                      pre_b2, post_b1, cbu);
    // (4) u-weights agg-part (P2 transpose/split)
    prep2<<<dim3(8, 8), dim3(32, 8)>>>(P2, wuh, wul, 512, 256);
    // (5) t = relu(a@Wt + bt)   <-- profiled launch
    mma_gemm<1><<<gg, 256, DSMEM>>>(ah, al, nullptr, nullptr, wth, wtl, cbt,
                                    th, tl, NN, 256, 256);

    // ---- CSR build + atomic-free segment sum ----
    cudaMemsetAsync(cnt, 0, NN * sizeof(int), 0);
    count_kernel<<<(NE + 255) / 256, 256>>>(dst, cnt);
    scan_kernel<<<1, 1024>>>(cnt, rowptr, fill);
    scatter_kernel<<<(NE + 255) / 256, 256>>>(src, dst, fill, col);
    agg_kernel<<<(NN + 3) / 4, 128>>>(th, tl, rowptr, col, gh, gl);

    // ---- u = relu(a@Wp + agg@P2 + bu)  (K=512 concat) ----
    mma_gemm<1><<<gg, 256, DSMEM>>>(ah, al, gh, gl, wuh, wul, cbu,
                                    uh, ul, NN, 512, 256);
    // ---- out = tanh(u@post_w2 + post_b2) ----
    out_kernel<<<(NN + 127) / 128, 256>>>(uh, ul, post_w2, post_b2, out, NN);
}